// round 9
// baseline (speedup 1.0000x reference)
#include <cuda_runtime.h>
#include <cuda_bf16.h>
#include <cuda_fp16.h>
#include <math.h>
#include <stdint.h>
#include <stddef.h>

#define BATCH 4
#define SEQ 1024
#define DMODEL 1024
#define NH 16
#define HD 64
#define NROWS (BATCH*SEQ)          // 4096

#define PITCH 40                   // 16b row pitch for 32-wide K tiles
#define PITCHV 72                  // 16b row pitch for 64-wide V tiles

// proj smem (dynamic): A 128x32 hi/lo + B 64x32 hi/lo, x2 buffers
#define SZA (128*PITCH*2)          // 10240
#define SZBB (64*PITCH*2)          // 5120
#define PBUF (2*SZA + 2*SZBB)      // 30720
#define PROJ_SMEM (2*PBUF)         // 61440

// Scratch (static device globals: allowed; no runtime allocation)
__device__ float g_qp[NROWS*DMODEL];
__device__ float g_kp[NROWS*DMODEL];
__device__ float g_vp[NROWS*DMODEL];
__device__ float g_ctx[NROWS*DMODEL];
__device__ __half g_p16[(size_t)NH*BATCH*SEQ*SEQ];   // unnormalized P (fp16)
__device__ float g_rspart[64*1024*8];
__device__ float g_rowinv[64*1024];

// ---------------------------------------------------------------------------
// Helpers
// ---------------------------------------------------------------------------
__device__ __forceinline__ uint32_t cvta_s(const void* p) {
    return (uint32_t)__cvta_generic_to_shared(p);
}

__device__ __forceinline__ void ldsm4(uint32_t* r, uint32_t addr) {
    asm volatile("ldmatrix.sync.aligned.m8n8.x4.shared.b16 {%0,%1,%2,%3}, [%4];"
                 : "=r"(r[0]), "=r"(r[1]), "=r"(r[2]), "=r"(r[3]) : "r"(addr));
}

__device__ __forceinline__ void ldsm4t(uint32_t* r, uint32_t addr) {
    asm volatile("ldmatrix.sync.aligned.m8n8.x4.trans.shared.b16 {%0,%1,%2,%3}, [%4];"
                 : "=r"(r[0]), "=r"(r[1]), "=r"(r[2]), "=r"(r[3]) : "r"(addr));
}

__device__ __forceinline__ void mma_bf16(float* c, const uint32_t* a, const uint32_t* b) {
    asm volatile(
        "mma.sync.aligned.m16n8k16.row.col.f32.bf16.bf16.f32 "
        "{%0,%1,%2,%3}, {%4,%5,%6,%7}, {%8,%9}, {%0,%1,%2,%3};"
        : "+f"(c[0]), "+f"(c[1]), "+f"(c[2]), "+f"(c[3])
        : "r"(a[0]), "r"(a[1]), "r"(a[2]), "r"(a[3]), "r"(b[0]), "r"(b[1]));
}

__device__ __forceinline__ void mma_f16(float* c, const uint32_t* a, const uint32_t* b) {
    asm volatile(
        "mma.sync.aligned.m16n8k16.row.col.f32.f16.f16.f32 "
        "{%0,%1,%2,%3}, {%4,%5,%6,%7}, {%8,%9}, {%0,%1,%2,%3};"
        : "+f"(c[0]), "+f"(c[1]), "+f"(c[2]), "+f"(c[3])
        : "r"(a[0]), "r"(a[1]), "r"(a[2]), "r"(a[3]), "r"(b[0]), "r"(b[1]));
}

// bf16 hi/lo split
__device__ __forceinline__ void split2(float x, float y, uint32_t& hi, uint32_t& lo) {
    __nv_bfloat162 h = __floats2bfloat162_rn(x, y);
    float hx = __bfloat162float(h.x);
    float hy = __bfloat162float(h.y);
    __nv_bfloat162 l = __floats2bfloat162_rn(x - hx, y - hy);
    hi = *reinterpret_cast<uint32_t*>(&h);
    lo = *reinterpret_cast<uint32_t*>(&l);
}

// fp16 hi/lo split
__device__ __forceinline__ void split2h(float x, float y, uint32_t& hi, uint32_t& lo) {
    __half2 h = __floats2half2_rn(x, y);
    float hx = __half2float(__low2half(h));
    float hy = __half2float(__high2half(h));
    __half2 l = __floats2half2_rn(x - hx, y - hy);
    hi = *reinterpret_cast<uint32_t*>(&h);
    lo = *reinterpret_cast<uint32_t*>(&l);
}

__device__ __forceinline__ void sts2(uint32_t addr, uint32_t a, uint32_t b) {
    asm volatile("st.shared.v2.b32 [%0], {%1,%2};" :: "r"(addr), "r"(a), "r"(b) : "memory");
}

__device__ __forceinline__ void sts4(uint32_t addr, uint32_t a, uint32_t b,
                                     uint32_t c, uint32_t d) {
    asm volatile("st.shared.v4.b32 [%0], {%1,%2,%3,%4};"
                 :: "r"(addr), "r"(a), "r"(b), "r"(c), "r"(d) : "memory");
}

// split + store 32-row-group fp32 tile regs to hi/lo smem (bf16)
__device__ __forceinline__ void store_rows(uint32_t uh, uint32_t ul,
                                           const float4* v, int n, int rg, int ck) {
    for (int i = 0; i < n; i++) {
        int off2 = ((rg + 32 * i) * PITCH + ck * 4) * 2;
        uint32_t h0, l0, h1, l1;
        split2(v[i].x, v[i].y, h0, l0);
        split2(v[i].z, v[i].w, h1, l1);
        sts2(uh + off2, h0, h1);
        sts2(ul + off2, l0, l1);
    }
}

// ---------------------------------------------------------------------------
// Projections: 128x64 CTA tile, 2 CTAs/SM, double-buffered.
// warps: 2(m) x 4(n); warp tile 64x16.
// ---------------------------------------------------------------------------
__global__ void __launch_bounds__(256, 2) proj_mma_kernel(
    const float* __restrict__ q, const float* __restrict__ k, const float* __restrict__ v,
    const float* __restrict__ Wq, const float* __restrict__ bq,
    const float* __restrict__ Wk, const float* __restrict__ bk,
    const float* __restrict__ Wv, const float* __restrict__ bv)
{
    extern __shared__ __align__(16) char dynsm[];

    const float *X, *W, *bias; float* O;
    if (blockIdx.z == 0)      { X = q; W = Wq; bias = bq; O = g_qp; }
    else if (blockIdx.z == 1) { X = k; W = Wk; bias = bk; O = g_kp; }
    else                      { X = v; W = Wv; bias = bv; O = g_vp; }

    const int tid = threadIdx.x;
    const int w = tid >> 5, ln = tid & 31;
    const int wm = (w >> 2) * 64;         // 2 warps in m
    const int wn = (w & 3) * 16;          // 4 warps in n
    const int rg = tid >> 3;              // 0..31
    const int ck = tid & 7;
    const int row0 = blockIdx.y * 128, col0 = blockIdx.x * 64;

    const float* Ab = X + (size_t)(row0 + rg) * DMODEL + ck * 4;
    const float* Bb = W + (size_t)(col0 + rg) * DMODEL + ck * 4;   // rg<32: rows 0..31, +32

    const uint32_t sb = cvta_s(dynsm);

    float acc[4][2][4];
#pragma unroll
    for (int i = 0; i < 4; i++)
#pragma unroll
        for (int j = 0; j < 2; j++)
#pragma unroll
            for (int t = 0; t < 4; t++) acc[i][j][t] = 0.f;

    float4 ar[4], br[2];
#pragma unroll
    for (int i = 0; i < 4; i++)
        ar[i] = *(const float4*)(Ab + (size_t)i * 32 * DMODEL);
#pragma unroll
    for (int i = 0; i < 2; i++)
        br[i] = *(const float4*)(Bb + (size_t)i * 32 * DMODEL);
    store_rows(sb,            sb + SZA,          ar, 4, rg, ck);
    store_rows(sb + 2 * SZA,  sb + 2 * SZA + SZBB, br, 2, rg, ck);
    __syncthreads();

    const int NST = DMODEL / 32;
    for (int s = 0; s < NST; s++) {
        const uint32_t bc = sb + (uint32_t)(s & 1) * PBUF;

        if (s + 1 < NST) {
            const float* An = Ab + (size_t)(s + 1) * 32;
            const float* Bn = Bb + (size_t)(s + 1) * 32;
#pragma unroll
            for (int i = 0; i < 4; i++)
                ar[i] = *(const float4*)(An + (size_t)i * 32 * DMODEL);
#pragma unroll
            for (int i = 0; i < 2; i++)
                br[i] = *(const float4*)(Bn + (size_t)i * 32 * DMODEL);
        }

#pragma unroll
        for (int ks = 0; ks < 2; ks++) {
            uint32_t ah[4][4], al[4][4], bh[4], bl[4];
#pragma unroll
            for (int i = 0; i < 4; i++) {
                uint32_t off = (uint32_t)((wm + i * 16 + (ln & 15)) * PITCH) * 2
                             + (uint32_t)ks * 32 + (uint32_t)(ln >> 4) * 16;
                ldsm4(ah[i], bc + off);
                ldsm4(al[i], bc + SZA + off);
            }
            {
                uint32_t row = (uint32_t)(wn + ((ln >> 4) << 3) + (ln & 7));
                uint32_t off = row * PITCH * 2 + (uint32_t)ks * 32
                             + (uint32_t)((ln >> 3) & 1) * 16;
                ldsm4(bh, bc + 2 * SZA + off);
                ldsm4(bl, bc + 2 * SZA + SZBB + off);
            }
#pragma unroll
            for (int i = 0; i < 4; i++)
#pragma unroll
                for (int j = 0; j < 2; j++) {
                    const uint32_t* bhj = &bh[j * 2];
                    const uint32_t* blj = &bl[j * 2];
                    mma_bf16(acc[i][j], ah[i], bhj);
                    mma_bf16(acc[i][j], ah[i], blj);
                    mma_bf16(acc[i][j], al[i], bhj);
                }
        }

        if (s + 1 < NST) {
            const uint32_t bn = sb + (uint32_t)((s + 1) & 1) * PBUF;
            store_rows(bn,           bn + SZA,           ar, 4, rg, ck);
            store_rows(bn + 2 * SZA, bn + 2 * SZA + SZBB, br, 2, rg, ck);
        }
        __syncthreads();
    }

#pragma unroll
    for (int i = 0; i < 4; i++) {
        int r = row0 + wm + i * 16 + (ln >> 2);
#pragma unroll
        for (int j = 0; j < 2; j++) {
            int c = col0 + wn + j * 8 + 2 * (ln & 3);
            float b0 = bias[c], b1 = bias[c + 1];
            *(float2*)&O[(size_t)r * DMODEL + c] =
                make_float2(acc[i][j][0] + b0, acc[i][j][1] + b1);
            *(float2*)&O[(size_t)(r + 8) * DMODEL + c] =
                make_float2(acc[i][j][2] + b0, acc[i][j][3] + b1);
        }
    }
}

// ---------------------------------------------------------------------------
// Scores + exp: writes unnormalized P (fp16) to g_p16; row partials -> g_rspart.
// ---------------------------------------------------------------------------
__global__ void __launch_bounds__(256, 1) scores_exp_kernel(
    const unsigned char* __restrict__ masks)
{
    __shared__ __align__(16) __nv_bfloat16 sAh[128*PITCH];
    __shared__ __align__(16) __nv_bfloat16 sAl[128*PITCH];
    __shared__ __align__(16) __nv_bfloat16 sBh[128*PITCH];
    __shared__ __align__(16) __nv_bfloat16 sBl[128*PITCH];

    const int z = blockIdx.z, b = z >> 4, h = z & 15;
    const float* A  = g_qp + (size_t)b * SEQ * DMODEL + h * HD;
    const float* Bm = g_kp + (size_t)b * SEQ * DMODEL + h * HD;
    const int row0 = blockIdx.y * 128, col0 = blockIdx.x * 128;

    const int tid = threadIdx.x;
    const int w = tid >> 5, ln = tid & 31;
    const int wm = (w >> 2) * 64;
    const int wn = (w & 3) * 32;
    const int rg = tid >> 3;
    const int ck = tid & 7;

    const float* Ab = A + (size_t)(row0 + rg) * DMODEL + ck * 4;
    const float* Bb = Bm + (size_t)(col0 + rg) * DMODEL + ck * 4;

    float acc[4][4][4];
#pragma unroll
    for (int i = 0; i < 4; i++)
#pragma unroll
        for (int j = 0; j < 4; j++)
#pragma unroll
            for (int t = 0; t < 4; t++) acc[i][j][t] = 0.f;

    const uint32_t uAh = cvta_s(sAh), uAl = cvta_s(sAl);
    const uint32_t uBh = cvta_s(sBh), uBl = cvta_s(sBl);

    float4 ar[4], br[4];
#pragma unroll
    for (int i = 0; i < 4; i++) {
        ar[i] = *(const float4*)(Ab + (size_t)i * 32 * DMODEL);
        br[i] = *(const float4*)(Bb + (size_t)i * 32 * DMODEL);
    }

    for (int s = 0; s < 2; s++) {          // K = 64
        store_rows(uAh, uAl, ar, 4, rg, ck);
        store_rows(uBh, uBl, br, 4, rg, ck);
        __syncthreads();

        if (s == 0) {
#pragma unroll
            for (int i = 0; i < 4; i++) {
                ar[i] = *(const float4*)(Ab + 32 + (size_t)i * 32 * DMODEL);
                br[i] = *(const float4*)(Bb + 32 + (size_t)i * 32 * DMODEL);
            }
        }

#pragma unroll
        for (int ks = 0; ks < 2; ks++) {
            uint32_t ah[4][4], al[4][4], bh[2][4], bl[2][4];
#pragma unroll
            for (int i = 0; i < 4; i++) {
                uint32_t off = (uint32_t)((wm + i * 16 + (ln & 15)) * PITCH) * 2
                             + (uint32_t)ks * 32 + (uint32_t)(ln >> 4) * 16;
                ldsm4(ah[i], uAh + off);
                ldsm4(al[i], uAl + off);
            }
#pragma unroll
            for (int g = 0; g < 2; g++) {
                uint32_t row = (uint32_t)(wn + g * 16 + ((ln >> 4) << 3) + (ln & 7));
                uint32_t off = row * PITCH * 2 + (uint32_t)ks * 32
                             + (uint32_t)((ln >> 3) & 1) * 16;
                ldsm4(bh[g], uBh + off);
                ldsm4(bl[g], uBl + off);
            }
#pragma unroll
            for (int i = 0; i < 4; i++)
#pragma unroll
                for (int j = 0; j < 4; j++) {
                    const uint32_t* bhj = &bh[j >> 1][(j & 1) * 2];
                    const uint32_t* blj = &bl[j >> 1][(j & 1) * 2];
                    mma_bf16(acc[i][j], ah[i], bhj);
                    mma_bf16(acc[i][j], ah[i], blj);
                    mma_bf16(acc[i][j], al[i], bhj);
                }
        }
        __syncthreads();
    }

    // epilogue: exp + fp16 P write + row partials
    float rp0[4], rp1[4];
#pragma unroll
    for (int i = 0; i < 4; i++) { rp0[i] = 0.f; rp1[i] = 0.f; }

#pragma unroll
    for (int i = 0; i < 4; i++) {
        int r = wm + i * 16 + (ln >> 2);
        int gr = row0 + r;
#pragma unroll
        for (int j = 0; j < 4; j++) {
            int c = col0 + wn + j * 8 + 2 * (ln & 3);
            const unsigned char* mp = masks + ((size_t)b * SEQ + gr) * SEQ + c;
            uchar2 ma = *(const uchar2*)mp;
            uchar2 mb = *(const uchar2*)(mp + 8 * SEQ);
            float e00 = ma.x ? 0.f : __expf(0.125f * acc[i][j][0]);
            float e01 = ma.y ? 0.f : __expf(0.125f * acc[i][j][1]);
            float e10 = mb.x ? 0.f : __expf(0.125f * acc[i][j][2]);
            float e11 = mb.y ? 0.f : __expf(0.125f * acc[i][j][3]);
            rp0[i] += e00 + e01;
            rp1[i] += e10 + e11;
            __half2 p0 = __floats2half2_rn(e00, e01);
            __half2 p1 = __floats2half2_rn(e10, e11);
            *(__half2*)&g_p16[((size_t)z * SEQ + gr) * SEQ + c] = p0;
            *(__half2*)&g_p16[((size_t)z * SEQ + gr + 8) * SEQ + c] = p1;
        }
    }
#pragma unroll
    for (int i = 0; i < 4; i++) {
        rp0[i] += __shfl_xor_sync(0xffffffffu, rp0[i], 1);
        rp0[i] += __shfl_xor_sync(0xffffffffu, rp0[i], 2);
        rp1[i] += __shfl_xor_sync(0xffffffffu, rp1[i], 1);
        rp1[i] += __shfl_xor_sync(0xffffffffu, rp1[i], 2);
    }
    __syncthreads();
    float* sred = reinterpret_cast<float*>(sAh);
    if ((ln & 3) == 0) {
#pragma unroll
        for (int i = 0; i < 4; i++) {
            int r = wm + i * 16 + (ln >> 2);
            sred[(w & 3) * 128 + r] = rp0[i];
            sred[(w & 3) * 128 + r + 8] = rp1[i];
        }
    }
    __syncthreads();
    if (tid < 128) {
        float ssum = sred[tid] + sred[128 + tid] + sred[256 + tid] + sred[384 + tid];
        g_rspart[(((size_t)z * SEQ) + row0 + tid) * 8 + blockIdx.x] = ssum;
    }
}

// ---------------------------------------------------------------------------
// rowinv = 1 / sum(partials)
// ---------------------------------------------------------------------------
__global__ void rowinv_kernel()
{
    int r = blockIdx.x * 256 + threadIdx.x;
    const float4* p = (const float4*)&g_rspart[(size_t)r * 8];
    float4 a = p[0], b = p[1];
    g_rowinv[r] = 1.f / (a.x + a.y + a.z + a.w + b.x + b.y + b.z + b.w);
}

// ---------------------------------------------------------------------------
// AV: reads fp16 P (A operand directly), V split fp16 hi/lo (2 mma terms),
// writes normalized fp32 att (only writer) and normalized ctx.
// ---------------------------------------------------------------------------
__global__ void __launch_bounds__(256, 1) av_mma_kernel(float* __restrict__ att)
{
    __shared__ __align__(16) __half sPa[128*PITCH];
    __shared__ __align__(16) __half sVh[32*PITCHV];
    __shared__ __align__(16) __half sVl[32*PITCHV];

    int z = blockIdx.z;
    int b = z >> 4, h = z & 15;
    const float* V = g_vp + (size_t)b * SEQ * DMODEL + h * HD;
    float* C = g_ctx + (size_t)b * SEQ * DMODEL + h * HD;
    const int row0 = blockIdx.y * 128;

    const int tid = threadIdx.x;
    const int w = tid >> 5, ln = tid & 31;
    const int wm = (w >> 1) * 32;          // 4 warps in m
    const int wn = (w & 1) * 32;           // 2 warps in n
    const int prow = tid >> 1;             // 0..127 : P loader row
    const int pseg = tid & 1;              // 0/1 : 16-half segment
    const int vr = tid >> 4, vc = tid & 15;

    const __half* Pb = g_p16 + ((size_t)z * SEQ + row0 + prow) * SEQ + pseg * 16;
    float* attb = att + ((size_t)z * SEQ + row0 + prow) * SEQ + pseg * 16;
    const float invp = g_rowinv[((size_t)z << 10) + row0 + prow];
    const float* Vb = V + (size_t)vr * DMODEL + vc * 4;

    float acc[2][4][4];
#pragma unroll
    for (int i = 0; i < 2; i++)
#pragma unroll
        for (int j = 0; j < 4; j++)
#pragma unroll
            for (int t = 0; t < 4; t++) acc[i][j][t] = 0.f;

    const uint32_t uPa = cvta_s(sPa);
    const uint32_t uVh = cvta_s(sVh), uVl = cvta_s(sVl);

    uint4 pr0, pr1;
    float4 vrg[2];
    pr0 = *(const uint4*)(Pb);
    pr1 = *(const uint4*)(Pb + 8);
#pragma unroll
    for (int i = 0; i < 2; i++) vrg[i] = *(const float4*)(Vb + (size_t)i * 16 * DMODEL);

    const int NSTAGES = SEQ / 32;
    for (int s = 0; s < NSTAGES; s++) {
        // stage P (fp16) into smem; write normalized fp32 att
        {
            uint32_t base = uPa + (uint32_t)(prow * PITCH + pseg * 16) * 2;
            sts4(base,      pr0.x, pr0.y, pr0.z, pr0.w);
            sts4(base + 16, pr1.x, pr1.y, pr1.z, pr1.w);

            float* adst = attb + (size_t)s * 32;
            const uint32_t* pw[2] = {&pr0.x, &pr1.x};
#pragma unroll
            for (int q4 = 0; q4 < 2; q4++) {
#pragma unroll
                for (int c2 = 0; c2 < 4; c2++) {
                    __half2 hp = *reinterpret_cast<const __half2*>(&pw[q4][c2]);
                    float2 f = __half22float2(hp);
                    *(float2*)(adst + q4 * 8 + c2 * 2) =
                        make_float2(f.x * invp, f.y * invp);
                }
            }
        }
        // stage V (fp32 -> fp16 hi/lo) into smem
#pragma unroll
        for (int i = 0; i < 2; i++) {
            int r = vr + 16 * i;
            uint32_t h0, l0, h1, l1;
            split2h(vrg[i].x, vrg[i].y, h0, l0);
            split2h(vrg[i].z, vrg[i].w, h1, l1);
            int off2 = (r * PITCHV + vc * 4) * 2;
            sts2(uVh + off2, h0, h1);
            sts2(uVl + off2, l0, l1);
        }
        __syncthreads();

        if (s + 1 < NSTAGES) {
            pr0 = *(const uint4*)(Pb + (size_t)(s + 1) * 32);
            pr1 = *(const uint4*)(Pb + (size_t)(s + 1) * 32 + 8);
            const float* Vn = Vb + (size_t)(s + 1) * 32 * DMODEL;
#pragma unroll
            for (int i = 0; i < 2; i++) vrg[i] = *(const float4*)(Vn + (size_t)i * 16 * DMODEL);
        }

#pragma unroll
        for (int ks = 0; ks < 2; ks++) {
            uint32_t ah[2][4], bh[2][4], bl[2][4];
#pragma unroll
            for (int i = 0; i < 2; i++) {
                uint32_t off = (uint32_t)((wm + i * 16 + (ln & 15)) * PITCH) * 2
                             + (uint32_t)ks * 32 + (uint32_t)(ln >> 4) * 16;
                ldsm4(ah[i], uPa + off);
            }
#pragma unroll
            for (int g = 0; g < 2; g++) {
                uint32_t rk = (uint32_t)(ks * 16 + (((ln >> 3) & 1) << 3) + (ln & 7));
                uint32_t nc = (uint32_t)(wn + g * 16 + ((ln >> 4) << 3));
                uint32_t off = rk * PITCHV * 2 + nc * 2;
                ldsm4t(bh[g], uVh + off);
                ldsm4t(bl[g], uVl + off);
            }
#pragma unroll
            for (int i = 0; i < 2; i++)
#pragma unroll
                for (int j = 0; j < 4; j++) {
                    const uint32_t* bhj = &bh[j >> 1][(j & 1) * 2];
                    const uint32_t* blj = &bl[j >> 1][(j & 1) * 2];
                    mma_f16(acc[i][j], ah[i], bhj);
                    mma_f16(acc[i][j], ah[i], blj);
                }
        }
        __syncthreads();
    }

#pragma unroll
    for (int i = 0; i < 2; i++) {
        int r = row0 + wm + i * 16 + (ln >> 2);
        float iv0 = g_rowinv[((size_t)z << 10) + r];
        float iv1 = g_rowinv[((size_t)z << 10) + r + 8];
#pragma unroll
        for (int j = 0; j < 4; j++) {
            int c = wn + j * 8 + 2 * (ln & 3);
            *(float2*)&C[(size_t)r * DMODEL + c] =
                make_float2(acc[i][j][0] * iv0, acc[i][j][1] * iv0);
            *(float2*)&C[(size_t)(r + 8) * DMODEL + c] =
                make_float2(acc[i][j][2] * iv1, acc[i][j][3] * iv1);
        }
    }
}

// ---------------------------------------------------------------------------
// output = LayerNorm(qp + ctx) * g + b
// ---------------------------------------------------------------------------
__global__ void ln_kernel(float* __restrict__ out,
                          const float* __restrict__ gam,
                          const float* __restrict__ bet)
{
    __shared__ float reds[8];
    __shared__ float redq[8];
    __shared__ float stat[2];

    int row = blockIdx.x;
    const float* xq = g_qp + (size_t)row * DMODEL;
    const float* xc = g_ctx + (size_t)row * DMODEL;
    int j = threadIdx.x * 4;

    float4 a = *(const float4*)(xq + j);
    float4 c = *(const float4*)(xc + j);
    float x0 = a.x + c.x, x1 = a.y + c.y, x2 = a.z + c.z, x3 = a.w + c.w;

    float s = x0 + x1 + x2 + x3;
    float sq = x0 * x0 + x1 * x1 + x2 * x2 + x3 * x3;
#pragma unroll
    for (int o = 16; o; o >>= 1) {
        s += __shfl_xor_sync(0xffffffffu, s, o);
        sq += __shfl_xor_sync(0xffffffffu, sq, o);
    }
    if ((threadIdx.x & 31) == 0) { reds[threadIdx.x >> 5] = s; redq[threadIdx.x >> 5] = sq; }
    __syncthreads();
    if (threadIdx.x == 0) {
        float S = 0.f, Q = 0.f;
#pragma unroll
        for (int w = 0; w < 8; w++) { S += reds[w]; Q += redq[w]; }
        float mu = S * (1.0f / DMODEL);
        float var = Q * (1.0f / DMODEL) - mu * mu;
        stat[0] = mu;
        stat[1] = rsqrtf(var + 1e-6f);
    }
    __syncthreads();
    float mu = stat[0], r = stat[1];

    float4 g4 = *(const float4*)(gam + j);
    float4 b4 = *(const float4*)(bet + j);
    float4 o4;
    o4.x = (x0 - mu) * r * g4.x + b4.x;
    o4.y = (x1 - mu) * r * g4.y + b4.y;
    o4.z = (x2 - mu) * r * g4.z + b4.z;
    o4.w = (x3 - mu) * r * g4.w + b4.w;
    *(float4*)(out + (size_t)row * DMODEL + j) = o4;
}

// ---------------------------------------------------------------------------
extern "C" void kernel_launch(void* const* d_in, const int* in_sizes, int n_in,
                              void* d_out, int out_size)
{
    const float* q  = (const float*)d_in[0];
    const float* k  = (const float*)d_in[1];
    const float* v  = (const float*)d_in[2];
    const unsigned char* masks = (const unsigned char*)d_in[3];
    const float* Wq = (const float*)d_in[4];
    const float* bq = (const float*)d_in[5];
    const float* Wk = (const float*)d_in[6];
    const float* bk = (const float*)d_in[7];
    const float* Wv = (const float*)d_in[8];
    const float* bv = (const float*)d_in[9];
    const float* lng = (const float*)d_in[10];
    const float* lnb = (const float*)d_in[11];

    float* out = (float*)d_out;
    float* att = out + (size_t)BATCH * SEQ * DMODEL;

    cudaFuncSetAttribute(proj_mma_kernel,
                         cudaFuncAttributeMaxDynamicSharedMemorySize, PROJ_SMEM);

    proj_mma_kernel<<<dim3(DMODEL / 64, NROWS / 128, 3), 256, PROJ_SMEM>>>(
        q, k, v, Wq, bq, Wk, bk, Wv, bv);
    scores_exp_kernel<<<dim3(SEQ / 128, SEQ / 128, BATCH * NH), 256>>>(masks);
    rowinv_kernel<<<256, 256>>>();
    av_mma_kernel<<<dim3(1, SEQ / 128, BATCH * NH), 256>>>(att);
    ln_kernel<<<NROWS, 256>>>(out, lng, lnb);
}

// round 12
// speedup vs baseline: 1.1037x; 1.1037x over previous
#include <cuda_runtime.h>
#include <cuda_bf16.h>
#include <cuda_fp16.h>
#include <math.h>
#include <stdint.h>
#include <stddef.h>

#define BATCH 4
#define SEQ 1024
#define DMODEL 1024
#define NH 16
#define HD 64
#define NROWS (BATCH*SEQ)          // 4096

#define PITCH 40                   // 16b row pitch for 32-wide K tiles
#define PITCHV 72                  // 16b row pitch for 64-wide V tiles

// proj smem (dynamic): A 128x32 hi/lo + B 64x32 hi/lo, x2 buffers
#define SZA (128*PITCH*2)          // 10240
#define SZBB (64*PITCH*2)          // 5120
#define PBUF (2*SZA + 2*SZBB)      // 30720
#define PROJ_SMEM (2*PBUF)         // 61440

// av smem (dynamic, flat): [P0, P1, Vh0, Vh1, Vl0, Vl1]
#define SZP (128*PITCH*2)          // 10240
#define SZV (32*PITCHV*2)          // 4608
#define AV_OFF_P 0
#define AV_OFF_VH (2*SZP)                  // 20480
#define AV_OFF_VL (AV_OFF_VH + 2*SZV)      // 29696
#define AV_SMEM (AV_OFF_VL + 2*SZV)        // 38912

// Scratch (static device globals: allowed; no runtime allocation)
__device__ float g_qp[NROWS*DMODEL];
__device__ float g_kp[NROWS*DMODEL];
__device__ float g_vp[NROWS*DMODEL];
__device__ float g_ctx[NROWS*DMODEL];
__device__ __half g_p16[(size_t)NH*BATCH*SEQ*SEQ];   // unnormalized P (fp16)
__device__ float g_rspart[64*1024*8];
__device__ float g_rowinv[64*1024];

// ---------------------------------------------------------------------------
// Helpers
// ---------------------------------------------------------------------------
__device__ __forceinline__ uint32_t cvta_s(const void* p) {
    return (uint32_t)__cvta_generic_to_shared(p);
}

__device__ __forceinline__ void ldsm4(uint32_t* r, uint32_t addr) {
    asm volatile("ldmatrix.sync.aligned.m8n8.x4.shared.b16 {%0,%1,%2,%3}, [%4];"
                 : "=r"(r[0]), "=r"(r[1]), "=r"(r[2]), "=r"(r[3]) : "r"(addr));
}

__device__ __forceinline__ void ldsm4t(uint32_t* r, uint32_t addr) {
    asm volatile("ldmatrix.sync.aligned.m8n8.x4.trans.shared.b16 {%0,%1,%2,%3}, [%4];"
                 : "=r"(r[0]), "=r"(r[1]), "=r"(r[2]), "=r"(r[3]) : "r"(addr));
}

__device__ __forceinline__ void mma_bf16(float* c, const uint32_t* a, const uint32_t* b) {
    asm volatile(
        "mma.sync.aligned.m16n8k16.row.col.f32.bf16.bf16.f32 "
        "{%0,%1,%2,%3}, {%4,%5,%6,%7}, {%8,%9}, {%0,%1,%2,%3};"
        : "+f"(c[0]), "+f"(c[1]), "+f"(c[2]), "+f"(c[3])
        : "r"(a[0]), "r"(a[1]), "r"(a[2]), "r"(a[3]), "r"(b[0]), "r"(b[1]));
}

__device__ __forceinline__ void mma_f16(float* c, const uint32_t* a, const uint32_t* b) {
    asm volatile(
        "mma.sync.aligned.m16n8k16.row.col.f32.f16.f16.f32 "
        "{%0,%1,%2,%3}, {%4,%5,%6,%7}, {%8,%9}, {%0,%1,%2,%3};"
        : "+f"(c[0]), "+f"(c[1]), "+f"(c[2]), "+f"(c[3])
        : "r"(a[0]), "r"(a[1]), "r"(a[2]), "r"(a[3]), "r"(b[0]), "r"(b[1]));
}

// bf16 hi/lo split
__device__ __forceinline__ void split2(float x, float y, uint32_t& hi, uint32_t& lo) {
    __nv_bfloat162 h = __floats2bfloat162_rn(x, y);
    float hx = __bfloat162float(h.x);
    float hy = __bfloat162float(h.y);
    __nv_bfloat162 l = __floats2bfloat162_rn(x - hx, y - hy);
    hi = *reinterpret_cast<uint32_t*>(&h);
    lo = *reinterpret_cast<uint32_t*>(&l);
}

// fp16 hi/lo split
__device__ __forceinline__ void split2h(float x, float y, uint32_t& hi, uint32_t& lo) {
    __half2 h = __floats2half2_rn(x, y);
    float hx = __half2float(__low2half(h));
    float hy = __half2float(__high2half(h));
    __half2 l = __floats2half2_rn(x - hx, y - hy);
    hi = *reinterpret_cast<uint32_t*>(&h);
    lo = *reinterpret_cast<uint32_t*>(&l);
}

__device__ __forceinline__ void sts2(uint32_t addr, uint32_t a, uint32_t b) {
    asm volatile("st.shared.v2.b32 [%0], {%1,%2};" :: "r"(addr), "r"(a), "r"(b) : "memory");
}

__device__ __forceinline__ void sts4(uint32_t addr, uint32_t a, uint32_t b,
                                     uint32_t c, uint32_t d) {
    asm volatile("st.shared.v4.b32 [%0], {%1,%2,%3,%4};"
                 :: "r"(addr), "r"(a), "r"(b), "r"(c), "r"(d) : "memory");
}

// split + store 32-row-group fp32 tile regs to hi/lo smem (bf16)
__device__ __forceinline__ void store_rows(uint32_t uh, uint32_t ul,
                                           const float4* v, int n, int rg, int ck) {
    for (int i = 0; i < n; i++) {
        int off2 = ((rg + 32 * i) * PITCH + ck * 4) * 2;
        uint32_t h0, l0, h1, l1;
        split2(v[i].x, v[i].y, h0, l0);
        split2(v[i].z, v[i].w, h1, l1);
        sts2(uh + off2, h0, h1);
        sts2(ul + off2, l0, l1);
    }
}

// ---------------------------------------------------------------------------
// Projections: 128x64 CTA tile, 2 CTAs/SM, double-buffered.
// ---------------------------------------------------------------------------
__global__ void __launch_bounds__(256, 2) proj_mma_kernel(
    const float* __restrict__ q, const float* __restrict__ k, const float* __restrict__ v,
    const float* __restrict__ Wq, const float* __restrict__ bq,
    const float* __restrict__ Wk, const float* __restrict__ bk,
    const float* __restrict__ Wv, const float* __restrict__ bv)
{
    extern __shared__ __align__(16) char dynsm[];

    const float *X, *W, *bias; float* O;
    if (blockIdx.z == 0)      { X = q; W = Wq; bias = bq; O = g_qp; }
    else if (blockIdx.z == 1) { X = k; W = Wk; bias = bk; O = g_kp; }
    else                      { X = v; W = Wv; bias = bv; O = g_vp; }

    const int tid = threadIdx.x;
    const int w = tid >> 5, ln = tid & 31;
    const int wm = (w >> 2) * 64;
    const int wn = (w & 3) * 16;
    const int rg = tid >> 3;
    const int ck = tid & 7;
    const int row0 = blockIdx.y * 128, col0 = blockIdx.x * 64;

    const float* Ab = X + (size_t)(row0 + rg) * DMODEL + ck * 4;
    const float* Bb = W + (size_t)(col0 + rg) * DMODEL + ck * 4;

    const uint32_t sb = cvta_s(dynsm);

    float acc[4][2][4];
#pragma unroll
    for (int i = 0; i < 4; i++)
#pragma unroll
        for (int j = 0; j < 2; j++)
#pragma unroll
            for (int t = 0; t < 4; t++) acc[i][j][t] = 0.f;

    float4 ar[4], br[2];
#pragma unroll
    for (int i = 0; i < 4; i++)
        ar[i] = *(const float4*)(Ab + (size_t)i * 32 * DMODEL);
#pragma unroll
    for (int i = 0; i < 2; i++)
        br[i] = *(const float4*)(Bb + (size_t)i * 32 * DMODEL);
    store_rows(sb,            sb + SZA,          ar, 4, rg, ck);
    store_rows(sb + 2 * SZA,  sb + 2 * SZA + SZBB, br, 2, rg, ck);
    __syncthreads();

    const int NST = DMODEL / 32;
    for (int s = 0; s < NST; s++) {
        const uint32_t bc = sb + (uint32_t)(s & 1) * PBUF;

        if (s + 1 < NST) {
            const float* An = Ab + (size_t)(s + 1) * 32;
            const float* Bn = Bb + (size_t)(s + 1) * 32;
#pragma unroll
            for (int i = 0; i < 4; i++)
                ar[i] = *(const float4*)(An + (size_t)i * 32 * DMODEL);
#pragma unroll
            for (int i = 0; i < 2; i++)
                br[i] = *(const float4*)(Bn + (size_t)i * 32 * DMODEL);
        }

#pragma unroll
        for (int ks = 0; ks < 2; ks++) {
            uint32_t ah[4][4], al[4][4], bh[4], bl[4];
#pragma unroll
            for (int i = 0; i < 4; i++) {
                uint32_t off = (uint32_t)((wm + i * 16 + (ln & 15)) * PITCH) * 2
                             + (uint32_t)ks * 32 + (uint32_t)(ln >> 4) * 16;
                ldsm4(ah[i], bc + off);
                ldsm4(al[i], bc + SZA + off);
            }
            {
                uint32_t row = (uint32_t)(wn + ((ln >> 4) << 3) + (ln & 7));
                uint32_t off = row * PITCH * 2 + (uint32_t)ks * 32
                             + (uint32_t)((ln >> 3) & 1) * 16;
                ldsm4(bh, bc + 2 * SZA + off);
                ldsm4(bl, bc + 2 * SZA + SZBB + off);
            }
#pragma unroll
            for (int i = 0; i < 4; i++)
#pragma unroll
                for (int j = 0; j < 2; j++) {
                    const uint32_t* bhj = &bh[j * 2];
                    const uint32_t* blj = &bl[j * 2];
                    mma_bf16(acc[i][j], ah[i], bhj);
                    mma_bf16(acc[i][j], ah[i], blj);
                    mma_bf16(acc[i][j], al[i], bhj);
                }
        }

        if (s + 1 < NST) {
            const uint32_t bn = sb + (uint32_t)((s + 1) & 1) * PBUF;
            store_rows(bn,           bn + SZA,           ar, 4, rg, ck);
            store_rows(bn + 2 * SZA, bn + 2 * SZA + SZBB, br, 2, rg, ck);
        }
        __syncthreads();
    }

#pragma unroll
    for (int i = 0; i < 4; i++) {
        int r = row0 + wm + i * 16 + (ln >> 2);
#pragma unroll
        for (int j = 0; j < 2; j++) {
            int c = col0 + wn + j * 8 + 2 * (ln & 3);
            float b0 = bias[c], b1 = bias[c + 1];
            *(float2*)&O[(size_t)r * DMODEL + c] =
                make_float2(acc[i][j][0] + b0, acc[i][j][1] + b1);
            *(float2*)&O[(size_t)(r + 8) * DMODEL + c] =
                make_float2(acc[i][j][2] + b0, acc[i][j][3] + b1);
        }
    }
}

// ---------------------------------------------------------------------------
// Scores + exp: writes unnormalized P (fp16) to g_p16; partials.
// ---------------------------------------------------------------------------
__global__ void __launch_bounds__(256, 1) scores_exp_kernel(
    const unsigned char* __restrict__ masks)
{
    __shared__ __align__(16) __nv_bfloat16 sAh[128*PITCH];
    __shared__ __align__(16) __nv_bfloat16 sAl[128*PITCH];
    __shared__ __align__(16) __nv_bfloat16 sBh[128*PITCH];
    __shared__ __align__(16) __nv_bfloat16 sBl[128*PITCH];

    const int z = blockIdx.z, b = z >> 4, h = z & 15;
    const float* A  = g_qp + (size_t)b * SEQ * DMODEL + h * HD;
    const float* Bm = g_kp + (size_t)b * SEQ * DMODEL + h * HD;
    const int row0 = blockIdx.y * 128, col0 = blockIdx.x * 128;

    const int tid = threadIdx.x;
    const int w = tid >> 5, ln = tid & 31;
    const int wm = (w >> 2) * 64;
    const int wn = (w & 3) * 32;
    const int rg = tid >> 3;
    const int ck = tid & 7;

    const float* Ab = A + (size_t)(row0 + rg) * DMODEL + ck * 4;
    const float* Bb = Bm + (size_t)(col0 + rg) * DMODEL + ck * 4;

    float acc[4][4][4];
#pragma unroll
    for (int i = 0; i < 4; i++)
#pragma unroll
        for (int j = 0; j < 4; j++)
#pragma unroll
            for (int t = 0; t < 4; t++) acc[i][j][t] = 0.f;

    const uint32_t uAh = cvta_s(sAh), uAl = cvta_s(sAl);
    const uint32_t uBh = cvta_s(sBh), uBl = cvta_s(sBl);

    float4 ar[4], br[4];
#pragma unroll
    for (int i = 0; i < 4; i++) {
        ar[i] = *(const float4*)(Ab + (size_t)i * 32 * DMODEL);
        br[i] = *(const float4*)(Bb + (size_t)i * 32 * DMODEL);
    }

    for (int s = 0; s < 2; s++) {          // K = 64
        store_rows(uAh, uAl, ar, 4, rg, ck);
        store_rows(uBh, uBl, br, 4, rg, ck);
        __syncthreads();

        if (s == 0) {
#pragma unroll
            for (int i = 0; i < 4; i++) {
                ar[i] = *(const float4*)(Ab + 32 + (size_t)i * 32 * DMODEL);
                br[i] = *(const float4*)(Bb + 32 + (size_t)i * 32 * DMODEL);
            }
        }

#pragma unroll
        for (int ks = 0; ks < 2; ks++) {
            uint32_t ah[4][4], al[4][4], bh[2][4], bl[2][4];
#pragma unroll
            for (int i = 0; i < 4; i++) {
                uint32_t off = (uint32_t)((wm + i * 16 + (ln & 15)) * PITCH) * 2
                             + (uint32_t)ks * 32 + (uint32_t)(ln >> 4) * 16;
                ldsm4(ah[i], uAh + off);
                ldsm4(al[i], uAl + off);
            }
#pragma unroll
            for (int g = 0; g < 2; g++) {
                uint32_t row = (uint32_t)(wn + g * 16 + ((ln >> 4) << 3) + (ln & 7));
                uint32_t off = row * PITCH * 2 + (uint32_t)ks * 32
                             + (uint32_t)((ln >> 3) & 1) * 16;
                ldsm4(bh[g], uBh + off);
                ldsm4(bl[g], uBl + off);
            }
#pragma unroll
            for (int i = 0; i < 4; i++)
#pragma unroll
                for (int j = 0; j < 4; j++) {
                    const uint32_t* bhj = &bh[j >> 1][(j & 1) * 2];
                    const uint32_t* blj = &bl[j >> 1][(j & 1) * 2];
                    mma_bf16(acc[i][j], ah[i], bhj);
                    mma_bf16(acc[i][j], ah[i], blj);
                    mma_bf16(acc[i][j], al[i], bhj);
                }
        }
        __syncthreads();
    }

    // epilogue: exp + fp16 P write + row partials
    float rp0[4], rp1[4];
#pragma unroll
    for (int i = 0; i < 4; i++) { rp0[i] = 0.f; rp1[i] = 0.f; }

#pragma unroll
    for (int i = 0; i < 4; i++) {
        int r = wm + i * 16 + (ln >> 2);
        int gr = row0 + r;
#pragma unroll
        for (int j = 0; j < 4; j++) {
            int c = col0 + wn + j * 8 + 2 * (ln & 3);
            const unsigned char* mp = masks + ((size_t)b * SEQ + gr) * SEQ + c;
            uchar2 ma = *(const uchar2*)mp;
            uchar2 mb = *(const uchar2*)(mp + 8 * SEQ);
            float e00 = ma.x ? 0.f : __expf(0.125f * acc[i][j][0]);
            float e01 = ma.y ? 0.f : __expf(0.125f * acc[i][j][1]);
            float e10 = mb.x ? 0.f : __expf(0.125f * acc[i][j][2]);
            float e11 = mb.y ? 0.f : __expf(0.125f * acc[i][j][3]);
            rp0[i] += e00 + e01;
            rp1[i] += e10 + e11;
            __half2 p0 = __floats2half2_rn(e00, e01);
            __half2 p1 = __floats2half2_rn(e10, e11);
            *(__half2*)&g_p16[((size_t)z * SEQ + gr) * SEQ + c] = p0;
            *(__half2*)&g_p16[((size_t)z * SEQ + gr + 8) * SEQ + c] = p1;
        }
    }
#pragma unroll
    for (int i = 0; i < 4; i++) {
        rp0[i] += __shfl_xor_sync(0xffffffffu, rp0[i], 1);
        rp0[i] += __shfl_xor_sync(0xffffffffu, rp0[i], 2);
        rp1[i] += __shfl_xor_sync(0xffffffffu, rp1[i], 1);
        rp1[i] += __shfl_xor_sync(0xffffffffu, rp1[i], 2);
    }
    __syncthreads();
    float* sred = reinterpret_cast<float*>(sAh);
    if ((ln & 3) == 0) {
#pragma unroll
        for (int i = 0; i < 4; i++) {
            int r = wm + i * 16 + (ln >> 2);
            sred[(w & 3) * 128 + r] = rp0[i];
            sred[(w & 3) * 128 + r + 8] = rp1[i];
        }
    }
    __syncthreads();
    if (tid < 128) {
        float ssum = sred[tid] + sred[128 + tid] + sred[256 + tid] + sred[384 + tid];
        g_rspart[(((size_t)z * SEQ) + row0 + tid) * 8 + blockIdx.x] = ssum;
    }
}

// ---------------------------------------------------------------------------
// rowinv = 1 / sum(partials)
// ---------------------------------------------------------------------------
__global__ void rowinv_kernel()
{
    int r = blockIdx.x * 256 + threadIdx.x;
    const float4* p = (const float4*)&g_rspart[(size_t)r * 8];
    float4 a = p[0], b = p[1];
    g_rowinv[r] = 1.f / (a.x + a.y + a.z + a.w + b.x + b.y + b.z + b.w);
}

// ---------------------------------------------------------------------------
// AV: fp16 P as A operand; V fp16 hi/lo (2 mma terms). DOUBLE-BUFFERED
// (flat dynamic smem), one __syncthreads per stage; float4 att write-back.
// ---------------------------------------------------------------------------
__global__ void __launch_bounds__(256, 2) av_mma_kernel(float* __restrict__ att)
{
    extern __shared__ __align__(16) char dynsm[];
    const uint32_t sb = cvta_s(dynsm);
    const uint32_t uPa = sb + AV_OFF_P;
    const uint32_t uVh = sb + AV_OFF_VH;
    const uint32_t uVl = sb + AV_OFF_VL;

    int z = blockIdx.z;
    int b = z >> 4, h = z & 15;
    const float* V = g_vp + (size_t)b * SEQ * DMODEL + h * HD;
    float* C = g_ctx + (size_t)b * SEQ * DMODEL + h * HD;
    const int row0 = blockIdx.y * 128;

    const int tid = threadIdx.x;
    const int w = tid >> 5, ln = tid & 31;
    const int wm = (w >> 1) * 32;          // 4 warps in m
    const int wn = (w & 1) * 32;           // 2 warps in n
    const int prow = tid >> 1;             // 0..127 : P loader row
    const int pseg = tid & 1;              // 0/1 : 16-half segment
    const int vr = tid >> 4, vc = tid & 15;

    const __half* Pb = g_p16 + ((size_t)z * SEQ + row0 + prow) * SEQ + pseg * 16;
    float* attb = att + ((size_t)z * SEQ + row0 + prow) * SEQ + pseg * 16;
    const float invp = g_rowinv[((size_t)z << 10) + row0 + prow];
    const float* Vb = V + (size_t)vr * DMODEL + vc * 4;

    float acc[2][4][4];
#pragma unroll
    for (int i = 0; i < 2; i++)
#pragma unroll
        for (int j = 0; j < 4; j++)
#pragma unroll
            for (int t = 0; t < 4; t++) acc[i][j][t] = 0.f;

    uint4 pr0, pr1;
    float4 vrg[2];
    pr0 = *(const uint4*)(Pb);
    pr1 = *(const uint4*)(Pb + 8);
#pragma unroll
    for (int i = 0; i < 2; i++) vrg[i] = *(const float4*)(Vb + (size_t)i * 16 * DMODEL);

    const int NSTAGES = SEQ / 32;
    for (int s = 0; s < NSTAGES; s++) {
        const uint32_t pOff = (uint32_t)(s & 1) * SZP;
        const uint32_t vOff = (uint32_t)(s & 1) * SZV;

        // stage P (fp16) into smem buffer
        {
            uint32_t base = uPa + pOff + (uint32_t)(prow * PITCH + pseg * 16) * 2;
            sts4(base,      pr0.x, pr0.y, pr0.z, pr0.w);
            sts4(base + 16, pr1.x, pr1.y, pr1.z, pr1.w);
        }
        // stage V (fp32 -> fp16 hi/lo) into smem buffer
#pragma unroll
        for (int i = 0; i < 2; i++) {
            int r = vr + 16 * i;
            uint32_t h0, l0, h1, l1;
            split2h(vrg[i].x, vrg[i].y, h0, l0);
            split2h(vrg[i].z, vrg[i].w, h1, l1);
            uint32_t off2 = (uint32_t)(r * PITCHV + vc * 4) * 2;
            sts2(uVh + vOff + off2, h0, h1);
            sts2(uVl + vOff + off2, l0, l1);
        }
        // normalized att write-back (float4 x4, 64B-aligned base)
        {
            float* adst = attb + (size_t)s * 32;
            const uint32_t pw[8] = {pr0.x, pr0.y, pr0.z, pr0.w,
                                    pr1.x, pr1.y, pr1.z, pr1.w};
#pragma unroll
            for (int q4 = 0; q4 < 4; q4++) {
                float2 fa = __half22float2(*reinterpret_cast<const __half2*>(&pw[q4 * 2]));
                float2 fb = __half22float2(*reinterpret_cast<const __half2*>(&pw[q4 * 2 + 1]));
                *(float4*)(adst + q4 * 4) =
                    make_float4(fa.x * invp, fa.y * invp, fb.x * invp, fb.y * invp);
            }
        }
        __syncthreads();

        // prefetch next stage into regs (hidden under mma below)
        if (s + 1 < NSTAGES) {
            pr0 = *(const uint4*)(Pb + (size_t)(s + 1) * 32);
            pr1 = *(const uint4*)(Pb + (size_t)(s + 1) * 32 + 8);
            const float* Vn = Vb + (size_t)(s + 1) * 32 * DMODEL;
#pragma unroll
            for (int i = 0; i < 2; i++) vrg[i] = *(const float4*)(Vn + (size_t)i * 16 * DMODEL);
        }

        // compute on current buffer
#pragma unroll
        for (int ks = 0; ks < 2; ks++) {
            uint32_t ah[2][4], bh[2][4], bl[2][4];
#pragma unroll
            for (int i = 0; i < 2; i++) {
                uint32_t off = (uint32_t)((wm + i * 16 + (ln & 15)) * PITCH) * 2
                             + (uint32_t)ks * 32 + (uint32_t)(ln >> 4) * 16;
                ldsm4(ah[i], uPa + pOff + off);
            }
#pragma unroll
            for (int g = 0; g < 2; g++) {
                uint32_t rk = (uint32_t)(ks * 16 + (((ln >> 3) & 1) << 3) + (ln & 7));
                uint32_t nc = (uint32_t)(wn + g * 16 + ((ln >> 4) << 3));
                uint32_t off = rk * PITCHV * 2 + nc * 2;
                ldsm4t(bh[g], uVh + vOff + off);
                ldsm4t(bl[g], uVl + vOff + off);
            }
#pragma unroll
            for (int i = 0; i < 2; i++)
#pragma unroll
                for (int j = 0; j < 4; j++) {
                    const uint32_t* bhj = &bh[j >> 1][(j & 1) * 2];
                    const uint32_t* blj = &bl[j >> 1][(j & 1) * 2];
                    mma_f16(acc[i][j], ah[i], bhj);
                    mma_f16(acc[i][j], ah[i], blj);
                }
        }
    }

#pragma unroll
    for (int i = 0; i < 2; i++) {
        int r = row0 + wm + i * 16 + (ln >> 2);
        float iv0 = g_rowinv[((size_t)z << 10) + r];
        float iv1 = g_rowinv[((size_t)z << 10) + r + 8];
#pragma unroll
        for (int j = 0; j < 4; j++) {
            int c = wn + j * 8 + 2 * (ln & 3);
            *(float2*)&C[(size_t)r * DMODEL + c] =
                make_float2(acc[i][j][0] * iv0, acc[i][j][1] * iv0);
            *(float2*)&C[(size_t)(r + 8) * DMODEL + c] =
                make_float2(acc[i][j][2] * iv1, acc[i][j][3] * iv1);
        }
    }
}

// ---------------------------------------------------------------------------
// output = LayerNorm(qp + ctx) * g + b
// ---------------------------------------------------------------------------
__global__ void ln_kernel(float* __restrict__ out,
                          const float* __restrict__ gam,
                          const float* __restrict__ bet)
{
    __shared__ float reds[8];
    __shared__ float redq[8];
    __shared__ float stat[2];

    int row = blockIdx.x;
    const float* xq = g_qp + (size_t)row * DMODEL;
    const float* xc = g_ctx + (size_t)row * DMODEL;
    int j = threadIdx.x * 4;

    float4 a = *(const float4*)(xq + j);
    float4 c = *(const float4*)(xc + j);
    float x0 = a.x + c.x, x1 = a.y + c.y, x2 = a.z + c.z, x3 = a.w + c.w;

    float s = x0 + x1 + x2 + x3;
    float sq = x0 * x0 + x1 * x1 + x2 * x2 + x3 * x3;
#pragma unroll
    for (int o = 16; o; o >>= 1) {
        s += __shfl_xor_sync(0xffffffffu, s, o);
        sq += __shfl_xor_sync(0xffffffffu, sq, o);
    }
    if ((threadIdx.x & 31) == 0) { reds[threadIdx.x >> 5] = s; redq[threadIdx.x >> 5] = sq; }
    __syncthreads();
    if (threadIdx.x == 0) {
        float S = 0.f, Q = 0.f;
#pragma unroll
        for (int w = 0; w < 8; w++) { S += reds[w]; Q += redq[w]; }
        float mu = S * (1.0f / DMODEL);
        float var = Q * (1.0f / DMODEL) - mu * mu;
        stat[0] = mu;
        stat[1] = rsqrtf(var + 1e-6f);
    }
    __syncthreads();
    float mu = stat[0], r = stat[1];

    float4 g4 = *(const float4*)(gam + j);
    float4 b4 = *(const float4*)(bet + j);
    float4 o4;
    o4.x = (x0 - mu) * r * g4.x + b4.x;
    o4.y = (x1 - mu) * r * g4.y + b4.y;
    o4.z = (x2 - mu) * r * g4.z + b4.z;
    o4.w = (x3 - mu) * r * g4.w + b4.w;
    *(float4*)(out + (size_t)row * DMODEL + j) = o4;
}

// ---------------------------------------------------------------------------
extern "C" void kernel_launch(void* const* d_in, const int* in_sizes, int n_in,
                              void* d_out, int out_size)
{
    const float* q  = (const float*)d_in[0];
    const float* k  = (const float*)d_in[1];
    const float* v  = (const float*)d_in[2];
    const unsigned char* masks = (const unsigned char*)d_in[3];
    const float* Wq = (const float*)d_in[4];
    const float* bq = (const float*)d_in[5];
    const float* Wk = (const float*)d_in[6];
    const float* bk = (const float*)d_in[7];
    const float* Wv = (const float*)d_in[8];
    const float* bv = (const float*)d_in[9];
    const float* lng = (const float*)d_in[10];
    const float* lnb = (const float*)d_in[11];

    float* out = (float*)d_out;
    float* att = out + (size_t)BATCH * SEQ * DMODEL;

    cudaFuncSetAttribute(proj_mma_kernel,
                         cudaFuncAttributeMaxDynamicSharedMemorySize, PROJ_SMEM);
    cudaFuncSetAttribute(av_mma_kernel,
                         cudaFuncAttributeMaxDynamicSharedMemorySize, AV_SMEM);

    proj_mma_kernel<<<dim3(DMODEL / 64, NROWS / 128, 3), 256, PROJ_SMEM>>>(
        q, k, v, Wq, bq, Wk, bk, Wv, bv);
    scores_exp_kernel<<<dim3(SEQ / 128, SEQ / 128, BATCH * NH), 256>>>(masks);
    rowinv_kernel<<<256, 256>>>();
    av_mma_kernel<<<dim3(1, SEQ / 128, BATCH * NH), 256, AV_SMEM>>>(att);
    ln_kernel<<<NROWS, 256>>>(out, lng, lnb);
}

// round 14
// speedup vs baseline: 1.2904x; 1.1691x over previous
#include <cuda_runtime.h>
#include <cuda_bf16.h>
#include <cuda_fp16.h>
#include <math.h>
#include <stdint.h>
#include <stddef.h>

#define BATCH 4
#define SEQ 1024
#define DMODEL 1024
#define NH 16
#define HD 64
#define NROWS (BATCH*SEQ)          // 4096

#define PITCH 40                   // 16b row pitch for 32-wide K tiles
#define PITCHV 72                  // 16b row pitch for 64-wide V tiles

// proj smem (dynamic): A 128x32 fp16 + B 64x32 fp16 hi/lo, x2 buffers
#define SZA (128*PITCH*2)          // 10240
#define SZBB (64*PITCH*2)          // 5120
#define PBUF (SZA + 2*SZBB)        // 20480
#define PROJ_SMEM (2*PBUF)         // 40960

// av smem (dynamic, flat): [P0, P1, Vh0, Vh1, Vl0, Vl1]
#define SZP (128*PITCH*2)          // 10240
#define SZV (32*PITCHV*2)          // 4608
#define AV_OFF_P 0
#define AV_OFF_VH (2*SZP)                  // 20480
#define AV_OFF_VL (AV_OFF_VH + 2*SZV)      // 29696
#define AV_SMEM (AV_OFF_VL + 2*SZV)        // 38912

// Scratch (static device globals: allowed; no runtime allocation)
__device__ float g_qp[NROWS*DMODEL];
__device__ float g_kp[NROWS*DMODEL];
__device__ float g_vp[NROWS*DMODEL];
__device__ float g_ctx[NROWS*DMODEL];
__device__ __half g_p16[(size_t)NH*BATCH*SEQ*SEQ];   // unnormalized P (fp16)
__device__ float g_rspart[64*1024*8];
__device__ float g_rowinv[64*1024];

// ---------------------------------------------------------------------------
// Helpers
// ---------------------------------------------------------------------------
__device__ __forceinline__ uint32_t cvta_s(const void* p) {
    return (uint32_t)__cvta_generic_to_shared(p);
}

__device__ __forceinline__ void ldsm4(uint32_t* r, uint32_t addr) {
    asm volatile("ldmatrix.sync.aligned.m8n8.x4.shared.b16 {%0,%1,%2,%3}, [%4];"
                 : "=r"(r[0]), "=r"(r[1]), "=r"(r[2]), "=r"(r[3]) : "r"(addr));
}

__device__ __forceinline__ void ldsm4t(uint32_t* r, uint32_t addr) {
    asm volatile("ldmatrix.sync.aligned.m8n8.x4.trans.shared.b16 {%0,%1,%2,%3}, [%4];"
                 : "=r"(r[0]), "=r"(r[1]), "=r"(r[2]), "=r"(r[3]) : "r"(addr));
}

__device__ __forceinline__ void mma_f16(float* c, const uint32_t* a, const uint32_t* b) {
    asm volatile(
        "mma.sync.aligned.m16n8k16.row.col.f32.f16.f16.f32 "
        "{%0,%1,%2,%3}, {%4,%5,%6,%7}, {%8,%9}, {%0,%1,%2,%3};"
        : "+f"(c[0]), "+f"(c[1]), "+f"(c[2]), "+f"(c[3])
        : "r"(a[0]), "r"(a[1]), "r"(a[2]), "r"(a[3]), "r"(b[0]), "r"(b[1]));
}

// fp16 hi/lo split
__device__ __forceinline__ void split2h(float x, float y, uint32_t& hi, uint32_t& lo) {
    __half2 h = __floats2half2_rn(x, y);
    float hx = __half2float(__low2half(h));
    float hy = __half2float(__high2half(h));
    __half2 l = __floats2half2_rn(x - hx, y - hy);
    hi = *reinterpret_cast<uint32_t*>(&h);
    lo = *reinterpret_cast<uint32_t*>(&l);
}

// fp16 single pack
__device__ __forceinline__ uint32_t pack_h2(float x, float y) {
    __half2 h = __floats2half2_rn(x, y);
    return *reinterpret_cast<uint32_t*>(&h);
}

__device__ __forceinline__ void sts2(uint32_t addr, uint32_t a, uint32_t b) {
    asm volatile("st.shared.v2.b32 [%0], {%1,%2};" :: "r"(addr), "r"(a), "r"(b) : "memory");
}

__device__ __forceinline__ void sts4(uint32_t addr, uint32_t a, uint32_t b,
                                     uint32_t c, uint32_t d) {
    asm volatile("st.shared.v4.b32 [%0], {%1,%2,%3,%4};"
                 :: "r"(addr), "r"(a), "r"(b), "r"(c), "r"(d) : "memory");
}

// store n 32-row groups as single fp16
__device__ __forceinline__ void store_rows_1(uint32_t u,
                                             const float4* v, int n, int rg, int ck) {
    for (int i = 0; i < n; i++) {
        int off2 = ((rg + 32 * i) * PITCH + ck * 4) * 2;
        sts2(u + off2, pack_h2(v[i].x, v[i].y), pack_h2(v[i].z, v[i].w));
    }
}

// store n 32-row groups as fp16 hi/lo
__device__ __forceinline__ void store_rows_hl(uint32_t uh, uint32_t ul,
                                              const float4* v, int n, int rg, int ck) {
    for (int i = 0; i < n; i++) {
        int off2 = ((rg + 32 * i) * PITCH + ck * 4) * 2;
        uint32_t h0, l0, h1, l1;
        split2h(v[i].x, v[i].y, h0, l0);
        split2h(v[i].z, v[i].w, h1, l1);
        sts2(uh + off2, h0, h1);
        sts2(ul + off2, l0, l1);
    }
}

// ---------------------------------------------------------------------------
// Projections: 128x64 CTA tile, 2 CTAs/SM, double-buffered.
// A single fp16, B fp16 hi/lo -> 2 mma terms.
// ---------------------------------------------------------------------------
__global__ void __launch_bounds__(256, 2) proj_mma_kernel(
    const float* __restrict__ q, const float* __restrict__ k, const float* __restrict__ v,
    const float* __restrict__ Wq, const float* __restrict__ bq,
    const float* __restrict__ Wk, const float* __restrict__ bk,
    const float* __restrict__ Wv, const float* __restrict__ bv)
{
    extern __shared__ __align__(16) char dynsm[];

    const float *X, *W, *bias; float* O;
    if (blockIdx.z == 0)      { X = q; W = Wq; bias = bq; O = g_qp; }
    else if (blockIdx.z == 1) { X = k; W = Wk; bias = bk; O = g_kp; }
    else                      { X = v; W = Wv; bias = bv; O = g_vp; }

    const int tid = threadIdx.x;
    const int w = tid >> 5, ln = tid & 31;
    const int wm = (w >> 2) * 64;
    const int wn = (w & 3) * 16;
    const int rg = tid >> 3;
    const int ck = tid & 7;
    const int row0 = blockIdx.y * 128, col0 = blockIdx.x * 64;

    const float* Ab = X + (size_t)(row0 + rg) * DMODEL + ck * 4;
    const float* Bb = W + (size_t)(col0 + rg) * DMODEL + ck * 4;

    const uint32_t sb = cvta_s(dynsm);

    float acc[4][2][4];
#pragma unroll
    for (int i = 0; i < 4; i++)
#pragma unroll
        for (int j = 0; j < 2; j++)
#pragma unroll
            for (int t = 0; t < 4; t++) acc[i][j][t] = 0.f;

    float4 ar[4], br[2];
#pragma unroll
    for (int i = 0; i < 4; i++)
        ar[i] = *(const float4*)(Ab + (size_t)i * 32 * DMODEL);
#pragma unroll
    for (int i = 0; i < 2; i++)
        br[i] = *(const float4*)(Bb + (size_t)i * 32 * DMODEL);
    store_rows_1(sb, ar, 4, rg, ck);
    store_rows_hl(sb + SZA, sb + SZA + SZBB, br, 2, rg, ck);
    __syncthreads();

    const int NST = DMODEL / 32;
    for (int s = 0; s < NST; s++) {
        const uint32_t bc = sb + (uint32_t)(s & 1) * PBUF;

        if (s + 1 < NST) {
            const float* An = Ab + (size_t)(s + 1) * 32;
            const float* Bn = Bb + (size_t)(s + 1) * 32;
#pragma unroll
            for (int i = 0; i < 4; i++)
                ar[i] = *(const float4*)(An + (size_t)i * 32 * DMODEL);
#pragma unroll
            for (int i = 0; i < 2; i++)
                br[i] = *(const float4*)(Bn + (size_t)i * 32 * DMODEL);
        }

#pragma unroll
        for (int ks = 0; ks < 2; ks++) {
            uint32_t ah[4][4], bh[4], bl[4];
#pragma unroll
            for (int i = 0; i < 4; i++) {
                uint32_t off = (uint32_t)((wm + i * 16 + (ln & 15)) * PITCH) * 2
                             + (uint32_t)ks * 32 + (uint32_t)(ln >> 4) * 16;
                ldsm4(ah[i], bc + off);
            }
            {
                uint32_t row = (uint32_t)(wn + ((ln >> 4) << 3) + (ln & 7));
                uint32_t off = row * PITCH * 2 + (uint32_t)ks * 32
                             + (uint32_t)((ln >> 3) & 1) * 16;
                ldsm4(bh, bc + SZA + off);
                ldsm4(bl, bc + SZA + SZBB + off);
            }
#pragma unroll
            for (int i = 0; i < 4; i++)
#pragma unroll
                for (int j = 0; j < 2; j++) {
                    mma_f16(acc[i][j], ah[i], &bh[j * 2]);
                    mma_f16(acc[i][j], ah[i], &bl[j * 2]);
                }
        }

        if (s + 1 < NST) {
            const uint32_t bn = sb + (uint32_t)((s + 1) & 1) * PBUF;
            store_rows_1(bn, ar, 4, rg, ck);
            store_rows_hl(bn + SZA, bn + SZA + SZBB, br, 2, rg, ck);
        }
        __syncthreads();
    }

#pragma unroll
    for (int i = 0; i < 4; i++) {
        int r = row0 + wm + i * 16 + (ln >> 2);
#pragma unroll
        for (int j = 0; j < 2; j++) {
            int c = col0 + wn + j * 8 + 2 * (ln & 3);
            float b0 = bias[c], b1 = bias[c + 1];
            *(float2*)&O[(size_t)r * DMODEL + c] =
                make_float2(acc[i][j][0] + b0, acc[i][j][1] + b1);
            *(float2*)&O[(size_t)(r + 8) * DMODEL + c] =
                make_float2(acc[i][j][2] + b0, acc[i][j][3] + b1);
        }
    }
}

// ---------------------------------------------------------------------------
// Scores + exp: A=qp single fp16, B=kp fp16 hi/lo -> 2 mma terms.
// Writes unnormalized P (fp16) to g_p16; row partials -> g_rspart.
// ---------------------------------------------------------------------------
__global__ void __launch_bounds__(256, 1) scores_exp_kernel(
    const unsigned char* __restrict__ masks)
{
    __shared__ __align__(16) __half sA[128*PITCH];
    __shared__ __align__(16) __half sBh[128*PITCH];
    __shared__ __align__(16) __half sBl[128*PITCH];

    const int z = blockIdx.z, b = z >> 4, h = z & 15;
    const float* A  = g_qp + (size_t)b * SEQ * DMODEL + h * HD;
    const float* Bm = g_kp + (size_t)b * SEQ * DMODEL + h * HD;
    const int row0 = blockIdx.y * 128, col0 = blockIdx.x * 128;

    const int tid = threadIdx.x;
    const int w = tid >> 5, ln = tid & 31;
    const int wm = (w >> 2) * 64;
    const int wn = (w & 3) * 32;
    const int rg = tid >> 3;
    const int ck = tid & 7;

    const float* Ab = A + (size_t)(row0 + rg) * DMODEL + ck * 4;
    const float* Bb = Bm + (size_t)(col0 + rg) * DMODEL + ck * 4;

    float acc[4][4][4];
#pragma unroll
    for (int i = 0; i < 4; i++)
#pragma unroll
        for (int j = 0; j < 4; j++)
#pragma unroll
            for (int t = 0; t < 4; t++) acc[i][j][t] = 0.f;

    const uint32_t uA = cvta_s(sA);
    const uint32_t uBh = cvta_s(sBh), uBl = cvta_s(sBl);

    float4 ar[4], br[4];
#pragma unroll
    for (int i = 0; i < 4; i++) {
        ar[i] = *(const float4*)(Ab + (size_t)i * 32 * DMODEL);
        br[i] = *(const float4*)(Bb + (size_t)i * 32 * DMODEL);
    }

    for (int s = 0; s < 2; s++) {          // K = 64
        store_rows_1(uA, ar, 4, rg, ck);
        store_rows_hl(uBh, uBl, br, 4, rg, ck);
        __syncthreads();

        if (s == 0) {
#pragma unroll
            for (int i = 0; i < 4; i++) {
                ar[i] = *(const float4*)(Ab + 32 + (size_t)i * 32 * DMODEL);
                br[i] = *(const float4*)(Bb + 32 + (size_t)i * 32 * DMODEL);
            }
        }

#pragma unroll
        for (int ks = 0; ks < 2; ks++) {
            uint32_t ah[4][4], bh[2][4], bl[2][4];
#pragma unroll
            for (int i = 0; i < 4; i++) {
                uint32_t off = (uint32_t)((wm + i * 16 + (ln & 15)) * PITCH) * 2
                             + (uint32_t)ks * 32 + (uint32_t)(ln >> 4) * 16;
                ldsm4(ah[i], uA + off);
            }
#pragma unroll
            for (int g = 0; g < 2; g++) {
                uint32_t row = (uint32_t)(wn + g * 16 + ((ln >> 4) << 3) + (ln & 7));
                uint32_t off = row * PITCH * 2 + (uint32_t)ks * 32
                             + (uint32_t)((ln >> 3) & 1) * 16;
                ldsm4(bh[g], uBh + off);
                ldsm4(bl[g], uBl + off);
            }
#pragma unroll
            for (int i = 0; i < 4; i++)
#pragma unroll
                for (int j = 0; j < 4; j++) {
                    const uint32_t* bhj = &bh[j >> 1][(j & 1) * 2];
                    const uint32_t* blj = &bl[j >> 1][(j & 1) * 2];
                    mma_f16(acc[i][j], ah[i], bhj);
                    mma_f16(acc[i][j], ah[i], blj);
                }
        }
        __syncthreads();
    }

    // epilogue: exp + fp16 P write + row partials
    float rp0[4], rp1[4];
#pragma unroll
    for (int i = 0; i < 4; i++) { rp0[i] = 0.f; rp1[i] = 0.f; }

#pragma unroll
    for (int i = 0; i < 4; i++) {
        int r = wm + i * 16 + (ln >> 2);
        int gr = row0 + r;
#pragma unroll
        for (int j = 0; j < 4; j++) {
            int c = col0 + wn + j * 8 + 2 * (ln & 3);
            const unsigned char* mp = masks + ((size_t)b * SEQ + gr) * SEQ + c;
            uchar2 ma = *(const uchar2*)mp;
            uchar2 mb = *(const uchar2*)(mp + 8 * SEQ);
            float e00 = ma.x ? 0.f : __expf(0.125f * acc[i][j][0]);
            float e01 = ma.y ? 0.f : __expf(0.125f * acc[i][j][1]);
            float e10 = mb.x ? 0.f : __expf(0.125f * acc[i][j][2]);
            float e11 = mb.y ? 0.f : __expf(0.125f * acc[i][j][3]);
            rp0[i] += e00 + e01;
            rp1[i] += e10 + e11;
            __half2 p0 = __floats2half2_rn(e00, e01);
            __half2 p1 = __floats2half2_rn(e10, e11);
            *(__half2*)&g_p16[((size_t)z * SEQ + gr) * SEQ + c] = p0;
            *(__half2*)&g_p16[((size_t)z * SEQ + gr + 8) * SEQ + c] = p1;
        }
    }
#pragma unroll
    for (int i = 0; i < 4; i++) {
        rp0[i] += __shfl_xor_sync(0xffffffffu, rp0[i], 1);
        rp0[i] += __shfl_xor_sync(0xffffffffu, rp0[i], 2);
        rp1[i] += __shfl_xor_sync(0xffffffffu, rp1[i], 1);
        rp1[i] += __shfl_xor_sync(0xffffffffu, rp1[i], 2);
    }
    __syncthreads();
    float* sred = reinterpret_cast<float*>(sA);
    if ((ln & 3) == 0) {
#pragma unroll
        for (int i = 0; i < 4; i++) {
            int r = wm + i * 16 + (ln >> 2);
            sred[(w & 3) * 128 + r] = rp0[i];
            sred[(w & 3) * 128 + r + 8] = rp1[i];
        }
    }
    __syncthreads();
    if (tid < 128) {
        float ssum = sred[tid] + sred[128 + tid] + sred[256 + tid] + sred[384 + tid];
        g_rspart[(((size_t)z * SEQ) + row0 + tid) * 8 + blockIdx.x] = ssum;
    }
}

// ---------------------------------------------------------------------------
// rowinv = 1 / sum(partials)
// ---------------------------------------------------------------------------
__global__ void rowinv_kernel()
{
    int r = blockIdx.x * 256 + threadIdx.x;
    const float4* p = (const float4*)&g_rspart[(size_t)r * 8];
    float4 a = p[0], b = p[1];
    g_rowinv[r] = 1.f / (a.x + a.y + a.z + a.w + b.x + b.y + b.z + b.w);
}

// ---------------------------------------------------------------------------
// AV: fp16 P as A operand; V fp16 hi/lo (2 mma terms). DOUBLE-BUFFERED
// (flat dynamic smem), one __syncthreads per stage; float4 att write-back.
// (unchanged from R12 WIN)
// ---------------------------------------------------------------------------
__global__ void __launch_bounds__(256, 2) av_mma_kernel(float* __restrict__ att)
{
    extern __shared__ __align__(16) char dynsm[];
    const uint32_t sb = cvta_s(dynsm);
    const uint32_t uPa = sb + AV_OFF_P;
    const uint32_t uVh = sb + AV_OFF_VH;
    const uint32_t uVl = sb + AV_OFF_VL;

    int z = blockIdx.z;
    int b = z >> 4, h = z & 15;
    const float* V = g_vp + (size_t)b * SEQ * DMODEL + h * HD;
    float* C = g_ctx + (size_t)b * SEQ * DMODEL + h * HD;
    const int row0 = blockIdx.y * 128;

    const int tid = threadIdx.x;
    const int w = tid >> 5, ln = tid & 31;
    const int wm = (w >> 1) * 32;
    const int wn = (w & 1) * 32;
    const int prow = tid >> 1;
    const int pseg = tid & 1;
    const int vr = tid >> 4, vc = tid & 15;

    const __half* Pb = g_p16 + ((size_t)z * SEQ + row0 + prow) * SEQ + pseg * 16;
    float* attb = att + ((size_t)z * SEQ + row0 + prow) * SEQ + pseg * 16;
    const float invp = g_rowinv[((size_t)z << 10) + row0 + prow];
    const float* Vb = V + (size_t)vr * DMODEL + vc * 4;

    float acc[2][4][4];
#pragma unroll
    for (int i = 0; i < 2; i++)
#pragma unroll
        for (int j = 0; j < 4; j++)
#pragma unroll
            for (int t = 0; t < 4; t++) acc[i][j][t] = 0.f;

    uint4 pr0, pr1;
    float4 vrg[2];
    pr0 = *(const uint4*)(Pb);
    pr1 = *(const uint4*)(Pb + 8);
#pragma unroll
    for (int i = 0; i < 2; i++) vrg[i] = *(const float4*)(Vb + (size_t)i * 16 * DMODEL);

    const int NSTAGES = SEQ / 32;
    for (int s = 0; s < NSTAGES; s++) {
        const uint32_t pOff = (uint32_t)(s & 1) * SZP;
        const uint32_t vOff = (uint32_t)(s & 1) * SZV;

        {
            uint32_t base = uPa + pOff + (uint32_t)(prow * PITCH + pseg * 16) * 2;
            sts4(base,      pr0.x, pr0.y, pr0.z, pr0.w);
            sts4(base + 16, pr1.x, pr1.y, pr1.z, pr1.w);
        }
#pragma unroll
        for (int i = 0; i < 2; i++) {
            int r = vr + 16 * i;
            uint32_t h0, l0, h1, l1;
            split2h(vrg[i].x, vrg[i].y, h0, l0);
            split2h(vrg[i].z, vrg[i].w, h1, l1);
            uint32_t off2 = (uint32_t)(r * PITCHV + vc * 4) * 2;
            sts2(uVh + vOff + off2, h0, h1);
            sts2(uVl + vOff + off2, l0, l1);
        }
        {
            float* adst = attb + (size_t)s * 32;
            const uint32_t pw[8] = {pr0.x, pr0.y, pr0.z, pr0.w,
                                    pr1.x, pr1.y, pr1.z, pr1.w};
#pragma unroll
            for (int q4 = 0; q4 < 4; q4++) {
                float2 fa = __half22float2(*reinterpret_cast<const __half2*>(&pw[q4 * 2]));
                float2 fb = __half22float2(*reinterpret_cast<const __half2*>(&pw[q4 * 2 + 1]));
                *(float4*)(adst + q4 * 4) =
                    make_float4(fa.x * invp, fa.y * invp, fb.x * invp, fb.y * invp);
            }
        }
        __syncthreads();

        if (s + 1 < NSTAGES) {
            pr0 = *(const uint4*)(Pb + (size_t)(s + 1) * 32);
            pr1 = *(const uint4*)(Pb + (size_t)(s + 1) * 32 + 8);
            const float* Vn = Vb + (size_t)(s + 1) * 32 * DMODEL;
#pragma unroll
            for (int i = 0; i < 2; i++) vrg[i] = *(const float4*)(Vn + (size_t)i * 16 * DMODEL);
        }

#pragma unroll
        for (int ks = 0; ks < 2; ks++) {
            uint32_t ah[2][4], bh[2][4], bl[2][4];
#pragma unroll
            for (int i = 0; i < 2; i++) {
                uint32_t off = (uint32_t)((wm + i * 16 + (ln & 15)) * PITCH) * 2
                             + (uint32_t)ks * 32 + (uint32_t)(ln >> 4) * 16;
                ldsm4(ah[i], uPa + pOff + off);
            }
#pragma unroll
            for (int g = 0; g < 2; g++) {
                uint32_t rk = (uint32_t)(ks * 16 + (((ln >> 3) & 1) << 3) + (ln & 7));
                uint32_t nc = (uint32_t)(wn + g * 16 + ((ln >> 4) << 3));
                uint32_t off = rk * PITCHV * 2 + nc * 2;
                ldsm4t(bh[g], uVh + vOff + off);
                ldsm4t(bl[g], uVl + vOff + off);
            }
#pragma unroll
            for (int i = 0; i < 2; i++)
#pragma unroll
                for (int j = 0; j < 4; j++) {
                    const uint32_t* bhj = &bh[j >> 1][(j & 1) * 2];
                    const uint32_t* blj = &bl[j >> 1][(j & 1) * 2];
                    mma_f16(acc[i][j], ah[i], bhj);
                    mma_f16(acc[i][j], ah[i], blj);
                }
        }
    }

#pragma unroll
    for (int i = 0; i < 2; i++) {
        int r = row0 + wm + i * 16 + (ln >> 2);
        float iv0 = g_rowinv[((size_t)z << 10) + r];
        float iv1 = g_rowinv[((size_t)z << 10) + r + 8];
#pragma unroll
        for (int j = 0; j < 4; j++) {
            int c = wn + j * 8 + 2 * (ln & 3);
            *(float2*)&C[(size_t)r * DMODEL + c] =
                make_float2(acc[i][j][0] * iv0, acc[i][j][1] * iv0);
            *(float2*)&C[(size_t)(r + 8) * DMODEL + c] =
                make_float2(acc[i][j][2] * iv1, acc[i][j][3] * iv1);
        }
    }
}

// ---------------------------------------------------------------------------
// output = LayerNorm(qp + ctx) * g + b
// ---------------------------------------------------------------------------
__global__ void ln_kernel(float* __restrict__ out,
                          const float* __restrict__ gam,
                          const float* __restrict__ bet)
{
    __shared__ float reds[8];
    __shared__ float redq[8];
    __shared__ float stat[2];

    int row = blockIdx.x;
    const float* xq = g_qp + (size_t)row * DMODEL;
    const float* xc = g_ctx + (size_t)row * DMODEL;
    int j = threadIdx.x * 4;

    float4 a = *(const float4*)(xq + j);
    float4 c = *(const float4*)(xc + j);
    float x0 = a.x + c.x, x1 = a.y + c.y, x2 = a.z + c.z, x3 = a.w + c.w;

    float s = x0 + x1 + x2 + x3;
    float sq = x0 * x0 + x1 * x1 + x2 * x2 + x3 * x3;
#pragma unroll
    for (int o = 16; o; o >>= 1) {
        s += __shfl_xor_sync(0xffffffffu, s, o);
        sq += __shfl_xor_sync(0xffffffffu, sq, o);
    }
    if ((threadIdx.x & 31) == 0) { reds[threadIdx.x >> 5] = s; redq[threadIdx.x >> 5] = sq; }
    __syncthreads();
    if (threadIdx.x == 0) {
        float S = 0.f, Q = 0.f;
#pragma unroll
        for (int w = 0; w < 8; w++) { S += reds[w]; Q += redq[w]; }
        float mu = S * (1.0f / DMODEL);
        float var = Q * (1.0f / DMODEL) - mu * mu;
        stat[0] = mu;
        stat[1] = rsqrtf(var + 1e-6f);
    }
    __syncthreads();
    float mu = stat[0], r = stat[1];

    float4 g4 = *(const float4*)(gam + j);
    float4 b4 = *(const float4*)(bet + j);
    float4 o4;
    o4.x = (x0 - mu) * r * g4.x + b4.x;
    o4.y = (x1 - mu) * r * g4.y + b4.y;
    o4.z = (x2 - mu) * r * g4.z + b4.z;
    o4.w = (x3 - mu) * r * g4.w + b4.w;
    *(float4*)(out + (size_t)row * DMODEL + j) = o4;
}

// ---------------------------------------------------------------------------
extern "C" void kernel_launch(void* const* d_in, const int* in_sizes, int n_in,
                              void* d_out, int out_size)
{
    const float* q  = (const float*)d_in[0];
    const float* k  = (const float*)d_in[1];
    const float* v  = (const float*)d_in[2];
    const unsigned char* masks = (const unsigned char*)d_in[3];
    const float* Wq = (const float*)d_in[4];
    const float* bq = (const float*)d_in[5];
    const float* Wk = (const float*)d_in[6];
    const float* bk = (const float*)d_in[7];
    const float* Wv = (const float*)d_in[8];
    const float* bv = (const float*)d_in[9];
    const float* lng = (const float*)d_in[10];
    const float* lnb = (const float*)d_in[11];

    float* out = (float*)d_out;
    float* att = out + (size_t)BATCH * SEQ * DMODEL;

    cudaFuncSetAttribute(proj_mma_kernel,
                         cudaFuncAttributeMaxDynamicSharedMemorySize, PROJ_SMEM);
    cudaFuncSetAttribute(av_mma_kernel,
                         cudaFuncAttributeMaxDynamicSharedMemorySize, AV_SMEM);

    proj_mma_kernel<<<dim3(DMODEL / 64, NROWS / 128, 3), 256, PROJ_SMEM>>>(
        q, k, v, Wq, bq, Wk, bk, Wv, bv);
    scores_exp_kernel<<<dim3(SEQ / 128, SEQ / 128, BATCH * NH), 256>>>(masks);
    rowinv_kernel<<<256, 256>>>();
    av_mma_kernel<<<dim3(1, SEQ / 128, BATCH * NH), 256, AV_SMEM>>>(att);
    ln_kernel<<<NROWS, 256>>>(out, lng, lnb);
}

// round 15
// speedup vs baseline: 1.3770x; 1.0672x over previous
#include <cuda_runtime.h>
#include <cuda_bf16.h>
#include <cuda_fp16.h>
#include <math.h>
#include <stdint.h>
#include <stddef.h>

#define BATCH 4
#define SEQ 1024
#define DMODEL 1024
#define NH 16
#define HD 64
#define NROWS (BATCH*SEQ)          // 4096

#define PITCH 40                   // 16b row pitch for 32-wide K tiles
#define PITCHW 72                  // 16b row pitch for 64-wide rows

// proj smem (dynamic): A 128x32 fp16 + B 64x32 fp16 hi/lo, x2 buffers
#define SZA (128*PITCH*2)          // 10240
#define SZBB (64*PITCH*2)          // 5120
#define PBUF (SZA + 2*SZBB)        // 20480
#define PROJ_SMEM (2*PBUF)         // 40960

// av smem (dynamic, flat): P tiles 128x64 fp16, V tiles 64x64 fp16; x2 buffers
#define SZP64 (128*PITCHW*2)       // 18432
#define SZV64 (64*PITCHW*2)        // 9216
#define AV_OFF_P 0
#define AV_OFF_V (2*SZP64)                 // 36864
#define AV_SMEM (AV_OFF_V + 2*SZV64)       // 55296

// Scratch (static device globals: allowed; no runtime allocation)
__device__ float g_qp[NROWS*DMODEL];
__device__ float g_kp[NROWS*DMODEL];
__device__ float g_vp[NROWS*DMODEL];
__device__ float g_ctx[NROWS*DMODEL];
__device__ __half g_p16[(size_t)NH*BATCH*SEQ*SEQ];   // unnormalized P (fp16)
__device__ float g_rspart[64*1024*8];
__device__ float g_rowinv[64*1024];

// ---------------------------------------------------------------------------
// Helpers
// ---------------------------------------------------------------------------
__device__ __forceinline__ uint32_t cvta_s(const void* p) {
    return (uint32_t)__cvta_generic_to_shared(p);
}

__device__ __forceinline__ void ldsm4(uint32_t* r, uint32_t addr) {
    asm volatile("ldmatrix.sync.aligned.m8n8.x4.shared.b16 {%0,%1,%2,%3}, [%4];"
                 : "=r"(r[0]), "=r"(r[1]), "=r"(r[2]), "=r"(r[3]) : "r"(addr));
}

__device__ __forceinline__ void ldsm4t(uint32_t* r, uint32_t addr) {
    asm volatile("ldmatrix.sync.aligned.m8n8.x4.trans.shared.b16 {%0,%1,%2,%3}, [%4];"
                 : "=r"(r[0]), "=r"(r[1]), "=r"(r[2]), "=r"(r[3]) : "r"(addr));
}

__device__ __forceinline__ void mma_f16(float* c, const uint32_t* a, const uint32_t* b) {
    asm volatile(
        "mma.sync.aligned.m16n8k16.row.col.f32.f16.f16.f32 "
        "{%0,%1,%2,%3}, {%4,%5,%6,%7}, {%8,%9}, {%0,%1,%2,%3};"
        : "+f"(c[0]), "+f"(c[1]), "+f"(c[2]), "+f"(c[3])
        : "r"(a[0]), "r"(a[1]), "r"(a[2]), "r"(a[3]), "r"(b[0]), "r"(b[1]));
}

// fp16 hi/lo split
__device__ __forceinline__ void split2h(float x, float y, uint32_t& hi, uint32_t& lo) {
    __half2 h = __floats2half2_rn(x, y);
    float hx = __half2float(__low2half(h));
    float hy = __half2float(__high2half(h));
    __half2 l = __floats2half2_rn(x - hx, y - hy);
    hi = *reinterpret_cast<uint32_t*>(&h);
    lo = *reinterpret_cast<uint32_t*>(&l);
}

// fp16 single pack
__device__ __forceinline__ uint32_t pack_h2(float x, float y) {
    __half2 h = __floats2half2_rn(x, y);
    return *reinterpret_cast<uint32_t*>(&h);
}

__device__ __forceinline__ void sts2(uint32_t addr, uint32_t a, uint32_t b) {
    asm volatile("st.shared.v2.b32 [%0], {%1,%2};" :: "r"(addr), "r"(a), "r"(b) : "memory");
}

__device__ __forceinline__ void sts4(uint32_t addr, uint32_t a, uint32_t b,
                                     uint32_t c, uint32_t d) {
    asm volatile("st.shared.v4.b32 [%0], {%1,%2,%3,%4};"
                 :: "r"(addr), "r"(a), "r"(b), "r"(c), "r"(d) : "memory");
}

// store n 32-row groups as single fp16
__device__ __forceinline__ void store_rows_1(uint32_t u,
                                             const float4* v, int n, int rg, int ck) {
    for (int i = 0; i < n; i++) {
        int off2 = ((rg + 32 * i) * PITCH + ck * 4) * 2;
        sts2(u + off2, pack_h2(v[i].x, v[i].y), pack_h2(v[i].z, v[i].w));
    }
}

// store n 32-row groups as fp16 hi/lo
__device__ __forceinline__ void store_rows_hl(uint32_t uh, uint32_t ul,
                                              const float4* v, int n, int rg, int ck) {
    for (int i = 0; i < n; i++) {
        int off2 = ((rg + 32 * i) * PITCH + ck * 4) * 2;
        uint32_t h0, l0, h1, l1;
        split2h(v[i].x, v[i].y, h0, l0);
        split2h(v[i].z, v[i].w, h1, l1);
        sts2(uh + off2, h0, h1);
        sts2(ul + off2, l0, l1);
    }
}

// ---------------------------------------------------------------------------
// Projections: 128x64 CTA tile, 2 CTAs/SM, double-buffered.
// A single fp16, B fp16 hi/lo -> 2 mma terms. (unchanged from R14 WIN)
// ---------------------------------------------------------------------------
__global__ void __launch_bounds__(256, 2) proj_mma_kernel(
    const float* __restrict__ q, const float* __restrict__ k, const float* __restrict__ v,
    const float* __restrict__ Wq, const float* __restrict__ bq,
    const float* __restrict__ Wk, const float* __restrict__ bk,
    const float* __restrict__ Wv, const float* __restrict__ bv)
{
    extern __shared__ __align__(16) char dynsm[];

    const float *X, *W, *bias; float* O;
    if (blockIdx.z == 0)      { X = q; W = Wq; bias = bq; O = g_qp; }
    else if (blockIdx.z == 1) { X = k; W = Wk; bias = bk; O = g_kp; }
    else                      { X = v; W = Wv; bias = bv; O = g_vp; }

    const int tid = threadIdx.x;
    const int w = tid >> 5, ln = tid & 31;
    const int wm = (w >> 2) * 64;
    const int wn = (w & 3) * 16;
    const int rg = tid >> 3;
    const int ck = tid & 7;
    const int row0 = blockIdx.y * 128, col0 = blockIdx.x * 64;

    const float* Ab = X + (size_t)(row0 + rg) * DMODEL + ck * 4;
    const float* Bb = W + (size_t)(col0 + rg) * DMODEL + ck * 4;

    const uint32_t sb = cvta_s(dynsm);

    float acc[4][2][4];
#pragma unroll
    for (int i = 0; i < 4; i++)
#pragma unroll
        for (int j = 0; j < 2; j++)
#pragma unroll
            for (int t = 0; t < 4; t++) acc[i][j][t] = 0.f;

    float4 ar[4], br[2];
#pragma unroll
    for (int i = 0; i < 4; i++)
        ar[i] = *(const float4*)(Ab + (size_t)i * 32 * DMODEL);
#pragma unroll
    for (int i = 0; i < 2; i++)
        br[i] = *(const float4*)(Bb + (size_t)i * 32 * DMODEL);
    store_rows_1(sb, ar, 4, rg, ck);
    store_rows_hl(sb + SZA, sb + SZA + SZBB, br, 2, rg, ck);
    __syncthreads();

    const int NST = DMODEL / 32;
    for (int s = 0; s < NST; s++) {
        const uint32_t bc = sb + (uint32_t)(s & 1) * PBUF;

        if (s + 1 < NST) {
            const float* An = Ab + (size_t)(s + 1) * 32;
            const float* Bn = Bb + (size_t)(s + 1) * 32;
#pragma unroll
            for (int i = 0; i < 4; i++)
                ar[i] = *(const float4*)(An + (size_t)i * 32 * DMODEL);
#pragma unroll
            for (int i = 0; i < 2; i++)
                br[i] = *(const float4*)(Bn + (size_t)i * 32 * DMODEL);
        }

#pragma unroll
        for (int ks = 0; ks < 2; ks++) {
            uint32_t ah[4][4], bh[4], bl[4];
#pragma unroll
            for (int i = 0; i < 4; i++) {
                uint32_t off = (uint32_t)((wm + i * 16 + (ln & 15)) * PITCH) * 2
                             + (uint32_t)ks * 32 + (uint32_t)(ln >> 4) * 16;
                ldsm4(ah[i], bc + off);
            }
            {
                uint32_t row = (uint32_t)(wn + ((ln >> 4) << 3) + (ln & 7));
                uint32_t off = row * PITCH * 2 + (uint32_t)ks * 32
                             + (uint32_t)((ln >> 3) & 1) * 16;
                ldsm4(bh, bc + SZA + off);
                ldsm4(bl, bc + SZA + SZBB + off);
            }
#pragma unroll
            for (int i = 0; i < 4; i++)
#pragma unroll
                for (int j = 0; j < 2; j++) {
                    mma_f16(acc[i][j], ah[i], &bh[j * 2]);
                    mma_f16(acc[i][j], ah[i], &bl[j * 2]);
                }
        }

        if (s + 1 < NST) {
            const uint32_t bn = sb + (uint32_t)((s + 1) & 1) * PBUF;
            store_rows_1(bn, ar, 4, rg, ck);
            store_rows_hl(bn + SZA, bn + SZA + SZBB, br, 2, rg, ck);
        }
        __syncthreads();
    }

#pragma unroll
    for (int i = 0; i < 4; i++) {
        int r = row0 + wm + i * 16 + (ln >> 2);
#pragma unroll
        for (int j = 0; j < 2; j++) {
            int c = col0 + wn + j * 8 + 2 * (ln & 3);
            float b0 = bias[c], b1 = bias[c + 1];
            *(float2*)&O[(size_t)r * DMODEL + c] =
                make_float2(acc[i][j][0] + b0, acc[i][j][1] + b1);
            *(float2*)&O[(size_t)(r + 8) * DMODEL + c] =
                make_float2(acc[i][j][2] + b0, acc[i][j][3] + b1);
        }
    }
}

// ---------------------------------------------------------------------------
// Scores + exp: pure fp16 QK^T (1 mma term), 2 CTAs/SM.
// Writes unnormalized P (fp16) to g_p16; row partials -> g_rspart.
// ---------------------------------------------------------------------------
__global__ void __launch_bounds__(256, 2) scores_exp_kernel(
    const unsigned char* __restrict__ masks)
{
    __shared__ __align__(16) __half sA[128*PITCH];
    __shared__ __align__(16) __half sB[128*PITCH];

    const int z = blockIdx.z, b = z >> 4, h = z & 15;
    const float* A  = g_qp + (size_t)b * SEQ * DMODEL + h * HD;
    const float* Bm = g_kp + (size_t)b * SEQ * DMODEL + h * HD;
    const int row0 = blockIdx.y * 128, col0 = blockIdx.x * 128;

    const int tid = threadIdx.x;
    const int w = tid >> 5, ln = tid & 31;
    const int wm = (w >> 2) * 64;
    const int wn = (w & 3) * 32;
    const int rg = tid >> 3;
    const int ck = tid & 7;

    const float* Ab = A + (size_t)(row0 + rg) * DMODEL + ck * 4;
    const float* Bb = Bm + (size_t)(col0 + rg) * DMODEL + ck * 4;

    float acc[4][4][4];
#pragma unroll
    for (int i = 0; i < 4; i++)
#pragma unroll
        for (int j = 0; j < 4; j++)
#pragma unroll
            for (int t = 0; t < 4; t++) acc[i][j][t] = 0.f;

    const uint32_t uA = cvta_s(sA);
    const uint32_t uB = cvta_s(sB);

    float4 ar[4], br[4];
#pragma unroll
    for (int i = 0; i < 4; i++) {
        ar[i] = *(const float4*)(Ab + (size_t)i * 32 * DMODEL);
        br[i] = *(const float4*)(Bb + (size_t)i * 32 * DMODEL);
    }

    for (int s = 0; s < 2; s++) {          // K = 64
        store_rows_1(uA, ar, 4, rg, ck);
        store_rows_1(uB, br, 4, rg, ck);
        __syncthreads();

        if (s == 0) {
#pragma unroll
            for (int i = 0; i < 4; i++) {
                ar[i] = *(const float4*)(Ab + 32 + (size_t)i * 32 * DMODEL);
                br[i] = *(const float4*)(Bb + 32 + (size_t)i * 32 * DMODEL);
            }
        }

#pragma unroll
        for (int ks = 0; ks < 2; ks++) {
            uint32_t ah[4][4], bh[2][4];
#pragma unroll
            for (int i = 0; i < 4; i++) {
                uint32_t off = (uint32_t)((wm + i * 16 + (ln & 15)) * PITCH) * 2
                             + (uint32_t)ks * 32 + (uint32_t)(ln >> 4) * 16;
                ldsm4(ah[i], uA + off);
            }
#pragma unroll
            for (int g = 0; g < 2; g++) {
                uint32_t row = (uint32_t)(wn + g * 16 + ((ln >> 4) << 3) + (ln & 7));
                uint32_t off = row * PITCH * 2 + (uint32_t)ks * 32
                             + (uint32_t)((ln >> 3) & 1) * 16;
                ldsm4(bh[g], uB + off);
            }
#pragma unroll
            for (int i = 0; i < 4; i++)
#pragma unroll
                for (int j = 0; j < 4; j++)
                    mma_f16(acc[i][j], ah[i], &bh[j >> 1][(j & 1) * 2]);
        }
        __syncthreads();
    }

    // epilogue: exp + fp16 P write + row partials
    float rp0[4], rp1[4];
#pragma unroll
    for (int i = 0; i < 4; i++) { rp0[i] = 0.f; rp1[i] = 0.f; }

#pragma unroll
    for (int i = 0; i < 4; i++) {
        int r = wm + i * 16 + (ln >> 2);
        int gr = row0 + r;
#pragma unroll
        for (int j = 0; j < 4; j++) {
            int c = col0 + wn + j * 8 + 2 * (ln & 3);
            const unsigned char* mp = masks + ((size_t)b * SEQ + gr) * SEQ + c;
            uchar2 ma = *(const uchar2*)mp;
            uchar2 mb = *(const uchar2*)(mp + 8 * SEQ);
            float e00 = ma.x ? 0.f : __expf(0.125f * acc[i][j][0]);
            float e01 = ma.y ? 0.f : __expf(0.125f * acc[i][j][1]);
            float e10 = mb.x ? 0.f : __expf(0.125f * acc[i][j][2]);
            float e11 = mb.y ? 0.f : __expf(0.125f * acc[i][j][3]);
            rp0[i] += e00 + e01;
            rp1[i] += e10 + e11;
            __half2 p0 = __floats2half2_rn(e00, e01);
            __half2 p1 = __floats2half2_rn(e10, e11);
            *(__half2*)&g_p16[((size_t)z * SEQ + gr) * SEQ + c] = p0;
            *(__half2*)&g_p16[((size_t)z * SEQ + gr + 8) * SEQ + c] = p1;
        }
    }
#pragma unroll
    for (int i = 0; i < 4; i++) {
        rp0[i] += __shfl_xor_sync(0xffffffffu, rp0[i], 1);
        rp0[i] += __shfl_xor_sync(0xffffffffu, rp0[i], 2);
        rp1[i] += __shfl_xor_sync(0xffffffffu, rp1[i], 1);
        rp1[i] += __shfl_xor_sync(0xffffffffu, rp1[i], 2);
    }
    __syncthreads();
    float* sred = reinterpret_cast<float*>(sA);
    if ((ln & 3) == 0) {
#pragma unroll
        for (int i = 0; i < 4; i++) {
            int r = wm + i * 16 + (ln >> 2);
            sred[(w & 3) * 128 + r] = rp0[i];
            sred[(w & 3) * 128 + r + 8] = rp1[i];
        }
    }
    __syncthreads();
    if (tid < 128) {
        float ssum = sred[tid] + sred[128 + tid] + sred[256 + tid] + sred[384 + tid];
        g_rspart[(((size_t)z * SEQ) + row0 + tid) * 8 + blockIdx.x] = ssum;
    }
}

// ---------------------------------------------------------------------------
// rowinv = 1 / sum(partials)
// ---------------------------------------------------------------------------
__global__ void rowinv_kernel()
{
    int r = blockIdx.x * 256 + threadIdx.x;
    const float4* p = (const float4*)&g_rspart[(size_t)r * 8];
    float4 a = p[0], b = p[1];
    g_rowinv[r] = 1.f / (a.x + a.y + a.z + a.w + b.x + b.y + b.z + b.w);
}

// ---------------------------------------------------------------------------
// AV: fp16 P x fp16 V (single term). K-stage = 64 (16 stages), double-buffered,
// one __syncthreads per stage; float4 att write-back.
// ---------------------------------------------------------------------------
__global__ void __launch_bounds__(256, 2) av_mma_kernel(float* __restrict__ att)
{
    extern __shared__ __align__(16) char dynsm[];
    const uint32_t sb = cvta_s(dynsm);
    const uint32_t uPa = sb + AV_OFF_P;
    const uint32_t uVa = sb + AV_OFF_V;

    int z = blockIdx.z;
    int b = z >> 4, h = z & 15;
    const float* V = g_vp + (size_t)b * SEQ * DMODEL + h * HD;
    float* C = g_ctx + (size_t)b * SEQ * DMODEL + h * HD;
    const int row0 = blockIdx.y * 128;

    const int tid = threadIdx.x;
    const int w = tid >> 5, ln = tid & 31;
    const int wm = (w >> 1) * 32;          // 4 warps in m
    const int wn = (w & 1) * 32;           // 2 warps in n
    const int prow = tid >> 1;             // 0..127 : P loader row
    const int pseg = tid & 1;              // 0/1 : 32-half segment
    const int vr = tid >> 2, vq = tid & 3; // V loader: 64 rows x 4 chunks of 16

    const __half* Pb = g_p16 + ((size_t)z * SEQ + row0 + prow) * SEQ + pseg * 32;
    float* attb = att + ((size_t)z * SEQ + row0 + prow) * SEQ + pseg * 32;
    const float invp = g_rowinv[((size_t)z << 10) + row0 + prow];
    const float* Vb = V + (size_t)vr * DMODEL + vq * 16;

    float acc[2][4][4];
#pragma unroll
    for (int i = 0; i < 2; i++)
#pragma unroll
        for (int j = 0; j < 4; j++)
#pragma unroll
            for (int t = 0; t < 4; t++) acc[i][j][t] = 0.f;

    uint4 pp[4];
    float4 vv[4];
#pragma unroll
    for (int i = 0; i < 4; i++) pp[i] = *(const uint4*)(Pb + i * 8);
#pragma unroll
    for (int i = 0; i < 4; i++) vv[i] = *(const float4*)(Vb + i * 4);

    const int NSTAGES = SEQ / 64;
    for (int s = 0; s < NSTAGES; s++) {
        const uint32_t pOff = (uint32_t)(s & 1) * SZP64;
        const uint32_t vOff = (uint32_t)(s & 1) * SZV64;

        // stage P (fp16) into smem buffer: 4x sts4
        {
            uint32_t base = uPa + pOff + (uint32_t)(prow * PITCHW + pseg * 32) * 2;
#pragma unroll
            for (int i = 0; i < 4; i++)
                sts4(base + i * 16, pp[i].x, pp[i].y, pp[i].z, pp[i].w);
        }
        // stage V (fp32 -> fp16 single) into smem buffer: 2x sts4
        {
            uint32_t base = uVa + vOff + (uint32_t)(vr * PITCHW + vq * 16) * 2;
            uint32_t h0 = pack_h2(vv[0].x, vv[0].y), h1 = pack_h2(vv[0].z, vv[0].w);
            uint32_t h2 = pack_h2(vv[1].x, vv[1].y), h3 = pack_h2(vv[1].z, vv[1].w);
            uint32_t h4 = pack_h2(vv[2].x, vv[2].y), h5 = pack_h2(vv[2].z, vv[2].w);
            uint32_t h6 = pack_h2(vv[3].x, vv[3].y), h7 = pack_h2(vv[3].z, vv[3].w);
            sts4(base,      h0, h1, h2, h3);
            sts4(base + 16, h4, h5, h6, h7);
        }
        // normalized att write-back (float4 x8)
        {
            float* adst = attb + (size_t)s * 64;
#pragma unroll
            for (int q4 = 0; q4 < 4; q4++) {
                const uint32_t* pw = &pp[q4].x;
#pragma unroll
                for (int half4 = 0; half4 < 2; half4++) {
                    float2 fa = __half22float2(*reinterpret_cast<const __half2*>(&pw[half4 * 2]));
                    float2 fb = __half22float2(*reinterpret_cast<const __half2*>(&pw[half4 * 2 + 1]));
                    *(float4*)(adst + q4 * 8 + half4 * 4) =
                        make_float4(fa.x * invp, fa.y * invp, fb.x * invp, fb.y * invp);
                }
            }
        }
        __syncthreads();

        // prefetch next stage into regs (hidden under mma below)
        if (s + 1 < NSTAGES) {
            const __half* Pn = Pb + (size_t)(s + 1) * 64;
            const float* Vn = Vb + (size_t)(s + 1) * 64 * DMODEL;
#pragma unroll
            for (int i = 0; i < 4; i++) pp[i] = *(const uint4*)(Pn + i * 8);
#pragma unroll
            for (int i = 0; i < 4; i++) vv[i] = *(const float4*)(Vn + i * 4);
        }

        // compute on current buffer: 4 k16 sub-steps
#pragma unroll
        for (int ks = 0; ks < 4; ks++) {
            uint32_t ah[2][4], bh[2][4];
#pragma unroll
            for (int i = 0; i < 2; i++) {
                uint32_t off = (uint32_t)((wm + i * 16 + (ln & 15)) * PITCHW) * 2
                             + (uint32_t)ks * 32 + (uint32_t)(ln >> 4) * 16;
                ldsm4(ah[i], uPa + pOff + off);
            }
#pragma unroll
            for (int g = 0; g < 2; g++) {
                uint32_t rk = (uint32_t)(ks * 16 + (((ln >> 3) & 1) << 3) + (ln & 7));
                uint32_t nc = (uint32_t)(wn + g * 16 + ((ln >> 4) << 3));
                uint32_t off = rk * PITCHW * 2 + nc * 2;
                ldsm4t(bh[g], uVa + vOff + off);
            }
#pragma unroll
            for (int i = 0; i < 2; i++)
#pragma unroll
                for (int j = 0; j < 4; j++)
                    mma_f16(acc[i][j], ah[i], &bh[j >> 1][(j & 1) * 2]);
        }
    }

#pragma unroll
    for (int i = 0; i < 2; i++) {
        int r = row0 + wm + i * 16 + (ln >> 2);
        float iv0 = g_rowinv[((size_t)z << 10) + r];
        float iv1 = g_rowinv[((size_t)z << 10) + r + 8];
#pragma unroll
        for (int j = 0; j < 4; j++) {
            int c = wn + j * 8 + 2 * (ln & 3);
            *(float2*)&C[(size_t)r * DMODEL + c] =
                make_float2(acc[i][j][0] * iv0, acc[i][j][1] * iv0);
            *(float2*)&C[(size_t)(r + 8) * DMODEL + c] =
                make_float2(acc[i][j][2] * iv1, acc[i][j][3] * iv1);
        }
    }
}

// ---------------------------------------------------------------------------
// output = LayerNorm(qp + ctx) * g + b
// ---------------------------------------------------------------------------
__global__ void ln_kernel(float* __restrict__ out,
                          const float* __restrict__ gam,
                          const float* __restrict__ bet)
{
    __shared__ float reds[8];
    __shared__ float redq[8];
    __shared__ float stat[2];

    int row = blockIdx.x;
    const float* xq = g_qp + (size_t)row * DMODEL;
    const float* xc = g_ctx + (size_t)row * DMODEL;
    int j = threadIdx.x * 4;

    float4 a = *(const float4*)(xq + j);
    float4 c = *(const float4*)(xc + j);
    float x0 = a.x + c.x, x1 = a.y + c.y, x2 = a.z + c.z, x3 = a.w + c.w;

    float s = x0 + x1 + x2 + x3;
    float sq = x0 * x0 + x1 * x1 + x2 * x2 + x3 * x3;
#pragma unroll
    for (int o = 16; o; o >>= 1) {
        s += __shfl_xor_sync(0xffffffffu, s, o);
        sq += __shfl_xor_sync(0xffffffffu, sq, o);
    }
    if ((threadIdx.x & 31) == 0) { reds[threadIdx.x >> 5] = s; redq[threadIdx.x >> 5] = sq; }
    __syncthreads();
    if (threadIdx.x == 0) {
        float S = 0.f, Q = 0.f;
#pragma unroll
        for (int w = 0; w < 8; w++) { S += reds[w]; Q += redq[w]; }
        float mu = S * (1.0f / DMODEL);
        float var = Q * (1.0f / DMODEL) - mu * mu;
        stat[0] = mu;
        stat[1] = rsqrtf(var + 1e-6f);
    }
    __syncthreads();
    float mu = stat[0], r = stat[1];

    float4 g4 = *(const float4*)(gam + j);
    float4 b4 = *(const float4*)(bet + j);
    float4 o4;
    o4.x = (x0 - mu) * r * g4.x + b4.x;
    o4.y = (x1 - mu) * r * g4.y + b4.y;
    o4.z = (x2 - mu) * r * g4.z + b4.z;
    o4.w = (x3 - mu) * r * g4.w + b4.w;
    *(float4*)(out + (size_t)row * DMODEL + j) = o4;
}

// ---------------------------------------------------------------------------
extern "C" void kernel_launch(void* const* d_in, const int* in_sizes, int n_in,
                              void* d_out, int out_size)
{
    const float* q  = (const float*)d_in[0];
    const float* k  = (const float*)d_in[1];
    const float* v  = (const float*)d_in[2];
    const unsigned char* masks = (const unsigned char*)d_in[3];
    const float* Wq = (const float*)d_in[4];
    const float* bq = (const float*)d_in[5];
    const float* Wk = (const float*)d_in[6];
    const float* bk = (const float*)d_in[7];
    const float* Wv = (const float*)d_in[8];
    const float* bv = (const float*)d_in[9];
    const float* lng = (const float*)d_in[10];
    const float* lnb = (const float*)d_in[11];

    float* out = (float*)d_out;
    float* att = out + (size_t)BATCH * SEQ * DMODEL;

    cudaFuncSetAttribute(proj_mma_kernel,
                         cudaFuncAttributeMaxDynamicSharedMemorySize, PROJ_SMEM);
    cudaFuncSetAttribute(av_mma_kernel,
                         cudaFuncAttributeMaxDynamicSharedMemorySize, AV_SMEM);

    proj_mma_kernel<<<dim3(DMODEL / 64, NROWS / 128, 3), 256, PROJ_SMEM>>>(
        q, k, v, Wq, bq, Wk, bk, Wv, bv);
    scores_exp_kernel<<<dim3(SEQ / 128, SEQ / 128, BATCH * NH), 256>>>(masks);
    rowinv_kernel<<<256, 256>>>();
    av_mma_kernel<<<dim3(1, SEQ / 128, BATCH * NH), 256, AV_SMEM>>>(att);
    ln_kernel<<<NROWS, 256>>>(out, lng, lnb);
}

// round 17
// speedup vs baseline: 1.4624x; 1.0620x over previous
#include <cuda_runtime.h>
#include <cuda_bf16.h>
#include <cuda_fp16.h>
#include <math.h>
#include <stdint.h>
#include <stddef.h>

#define BATCH 4
#define SEQ 1024
#define DMODEL 1024
#define NH 16
#define HD 64
#define NROWS (BATCH*SEQ)          // 4096

#define PITCH 40                   // 16b row pitch for 32-wide K tiles
#define PITCHV 72                  // 16b row pitch for 64-wide V tiles

// proj smem (dynamic): A 128x32 fp16 + B 64x32 fp16 hi/lo, x2 buffers
#define SZA (128*PITCH*2)          // 10240
#define SZBB (64*PITCH*2)          // 5120
#define PBUF (SZA + 2*SZBB)        // 20480
#define PROJ_SMEM (2*PBUF)         // 40960

// av smem (dynamic, flat): [P0, P1, V0, V1]  (V single fp16)
#define SZP (128*PITCH*2)          // 10240
#define SZV (32*PITCHV*2)          // 4608
#define AV_OFF_P 0
#define AV_OFF_V (2*SZP)                   // 20480
#define AV_SMEM (AV_OFF_V + 2*SZV)         // 29696

// Scratch (static device globals: allowed; no runtime allocation)
__device__ float g_qp[NROWS*DMODEL];
__device__ float g_kp[NROWS*DMODEL];
__device__ float g_vp[NROWS*DMODEL];
__device__ float g_ctx[NROWS*DMODEL];
__device__ __half g_p16[(size_t)NH*BATCH*SEQ*SEQ];   // unnormalized P (fp16)
__device__ float g_rspart[64*1024*8];
__device__ float g_rowinv[64*1024];

// ---------------------------------------------------------------------------
// Helpers
// ---------------------------------------------------------------------------
__device__ __forceinline__ uint32_t cvta_s(const void* p) {
    return (uint32_t)__cvta_generic_to_shared(p);
}

__device__ __forceinline__ void ldsm4(uint32_t* r, uint32_t addr) {
    asm volatile("ldmatrix.sync.aligned.m8n8.x4.shared.b16 {%0,%1,%2,%3}, [%4];"
                 : "=r"(r[0]), "=r"(r[1]), "=r"(r[2]), "=r"(r[3]) : "r"(addr));
}

__device__ __forceinline__ void ldsm4t(uint32_t* r, uint32_t addr) {
    asm volatile("ldmatrix.sync.aligned.m8n8.x4.trans.shared.b16 {%0,%1,%2,%3}, [%4];"
                 : "=r"(r[0]), "=r"(r[1]), "=r"(r[2]), "=r"(r[3]) : "r"(addr));
}

__device__ __forceinline__ void mma_f16(float* c, const uint32_t* a, const uint32_t* b) {
    asm volatile(
        "mma.sync.aligned.m16n8k16.row.col.f32.f16.f16.f32 "
        "{%0,%1,%2,%3}, {%4,%5,%6,%7}, {%8,%9}, {%0,%1,%2,%3};"
        : "+f"(c[0]), "+f"(c[1]), "+f"(c[2]), "+f"(c[3])
        : "r"(a[0]), "r"(a[1]), "r"(a[2]), "r"(a[3]), "r"(b[0]), "r"(b[1]));
}

// fp16 hi/lo split
__device__ __forceinline__ void split2h(float x, float y, uint32_t& hi, uint32_t& lo) {
    __half2 h = __floats2half2_rn(x, y);
    float hx = __half2float(__low2half(h));
    float hy = __half2float(__high2half(h));
    __half2 l = __floats2half2_rn(x - hx, y - hy);
    hi = *reinterpret_cast<uint32_t*>(&h);
    lo = *reinterpret_cast<uint32_t*>(&l);
}

// fp16 single pack
__device__ __forceinline__ uint32_t pack_h2(float x, float y) {
    __half2 h = __floats2half2_rn(x, y);
    return *reinterpret_cast<uint32_t*>(&h);
}

__device__ __forceinline__ void sts2(uint32_t addr, uint32_t a, uint32_t b) {
    asm volatile("st.shared.v2.b32 [%0], {%1,%2};" :: "r"(addr), "r"(a), "r"(b) : "memory");
}

__device__ __forceinline__ void sts4(uint32_t addr, uint32_t a, uint32_t b,
                                     uint32_t c, uint32_t d) {
    asm volatile("st.shared.v4.b32 [%0], {%1,%2,%3,%4};"
                 :: "r"(addr), "r"(a), "r"(b), "r"(c), "r"(d) : "memory");
}

// store n 32-row groups as single fp16
__device__ __forceinline__ void store_rows_1(uint32_t u,
                                             const float4* v, int n, int rg, int ck) {
    for (int i = 0; i < n; i++) {
        int off2 = ((rg + 32 * i) * PITCH + ck * 4) * 2;
        sts2(u + off2, pack_h2(v[i].x, v[i].y), pack_h2(v[i].z, v[i].w));
    }
}

// store n 32-row groups as fp16 hi/lo
__device__ __forceinline__ void store_rows_hl(uint32_t uh, uint32_t ul,
                                              const float4* v, int n, int rg, int ck) {
    for (int i = 0; i < n; i++) {
        int off2 = ((rg + 32 * i) * PITCH + ck * 4) * 2;
        uint32_t h0, l0, h1, l1;
        split2h(v[i].x, v[i].y, h0, l0);
        split2h(v[i].z, v[i].w, h1, l1);
        sts2(uh + off2, h0, h1);
        sts2(ul + off2, l0, l1);
    }
}

// ---------------------------------------------------------------------------
// Projections: 128x64 CTA tile, 2 CTAs/SM, double-buffered.
// A single fp16, B fp16 hi/lo -> 2 mma terms. (unchanged from R14/R15 WIN)
// ---------------------------------------------------------------------------
__global__ void __launch_bounds__(256, 2) proj_mma_kernel(
    const float* __restrict__ q, const float* __restrict__ k, const float* __restrict__ v,
    const float* __restrict__ Wq, const float* __restrict__ bq,
    const float* __restrict__ Wk, const float* __restrict__ bk,
    const float* __restrict__ Wv, const float* __restrict__ bv)
{
    extern __shared__ __align__(16) char dynsm[];

    const float *X, *W, *bias; float* O;
    if (blockIdx.z == 0)      { X = q; W = Wq; bias = bq; O = g_qp; }
    else if (blockIdx.z == 1) { X = k; W = Wk; bias = bk; O = g_kp; }
    else                      { X = v; W = Wv; bias = bv; O = g_vp; }

    const int tid = threadIdx.x;
    const int w = tid >> 5, ln = tid & 31;
    const int wm = (w >> 2) * 64;
    const int wn = (w & 3) * 16;
    const int rg = tid >> 3;
    const int ck = tid & 7;
    const int row0 = blockIdx.y * 128, col0 = blockIdx.x * 64;

    const float* Ab = X + (size_t)(row0 + rg) * DMODEL + ck * 4;
    const float* Bb = W + (size_t)(col0 + rg) * DMODEL + ck * 4;

    const uint32_t sb = cvta_s(dynsm);

    float acc[4][2][4];
#pragma unroll
    for (int i = 0; i < 4; i++)
#pragma unroll
        for (int j = 0; j < 2; j++)
#pragma unroll
            for (int t = 0; t < 4; t++) acc[i][j][t] = 0.f;

    float4 ar[4], br[2];
#pragma unroll
    for (int i = 0; i < 4; i++)
        ar[i] = *(const float4*)(Ab + (size_t)i * 32 * DMODEL);
#pragma unroll
    for (int i = 0; i < 2; i++)
        br[i] = *(const float4*)(Bb + (size_t)i * 32 * DMODEL);
    store_rows_1(sb, ar, 4, rg, ck);
    store_rows_hl(sb + SZA, sb + SZA + SZBB, br, 2, rg, ck);
    __syncthreads();

    const int NST = DMODEL / 32;
    for (int s = 0; s < NST; s++) {
        const uint32_t bc = sb + (uint32_t)(s & 1) * PBUF;

        if (s + 1 < NST) {
            const float* An = Ab + (size_t)(s + 1) * 32;
            const float* Bn = Bb + (size_t)(s + 1) * 32;
#pragma unroll
            for (int i = 0; i < 4; i++)
                ar[i] = *(const float4*)(An + (size_t)i * 32 * DMODEL);
#pragma unroll
            for (int i = 0; i < 2; i++)
                br[i] = *(const float4*)(Bn + (size_t)i * 32 * DMODEL);
        }

#pragma unroll
        for (int ks = 0; ks < 2; ks++) {
            uint32_t ah[4][4], bh[4], bl[4];
#pragma unroll
            for (int i = 0; i < 4; i++) {
                uint32_t off = (uint32_t)((wm + i * 16 + (ln & 15)) * PITCH) * 2
                             + (uint32_t)ks * 32 + (uint32_t)(ln >> 4) * 16;
                ldsm4(ah[i], bc + off);
            }
            {
                uint32_t row = (uint32_t)(wn + ((ln >> 4) << 3) + (ln & 7));
                uint32_t off = row * PITCH * 2 + (uint32_t)ks * 32
                             + (uint32_t)((ln >> 3) & 1) * 16;
                ldsm4(bh, bc + SZA + off);
                ldsm4(bl, bc + SZA + SZBB + off);
            }
#pragma unroll
            for (int i = 0; i < 4; i++)
#pragma unroll
                for (int j = 0; j < 2; j++) {
                    mma_f16(acc[i][j], ah[i], &bh[j * 2]);
                    mma_f16(acc[i][j], ah[i], &bl[j * 2]);
                }
        }

        if (s + 1 < NST) {
            const uint32_t bn = sb + (uint32_t)((s + 1) & 1) * PBUF;
            store_rows_1(bn, ar, 4, rg, ck);
            store_rows_hl(bn + SZA, bn + SZA + SZBB, br, 2, rg, ck);
        }
        __syncthreads();
    }

#pragma unroll
    for (int i = 0; i < 4; i++) {
        int r = row0 + wm + i * 16 + (ln >> 2);
#pragma unroll
        for (int j = 0; j < 2; j++) {
            int c = col0 + wn + j * 8 + 2 * (ln & 3);
            float b0 = bias[c], b1 = bias[c + 1];
            *(float2*)&O[(size_t)r * DMODEL + c] =
                make_float2(acc[i][j][0] + b0, acc[i][j][1] + b1);
            *(float2*)&O[(size_t)(r + 8) * DMODEL + c] =
                make_float2(acc[i][j][2] + b0, acc[i][j][3] + b1);
        }
    }
}

// ---------------------------------------------------------------------------
// Scores + exp: pure fp16 QK^T (1 mma term), 2 CTAs/SM. (unchanged from R15 WIN)
// ---------------------------------------------------------------------------
__global__ void __launch_bounds__(256, 2) scores_exp_kernel(
    const unsigned char* __restrict__ masks)
{
    __shared__ __align__(16) __half sA[128*PITCH];
    __shared__ __align__(16) __half sB[128*PITCH];

    const int z = blockIdx.z, b = z >> 4, h = z & 15;
    const float* A  = g_qp + (size_t)b * SEQ * DMODEL + h * HD;
    const float* Bm = g_kp + (size_t)b * SEQ * DMODEL + h * HD;
    const int row0 = blockIdx.y * 128, col0 = blockIdx.x * 128;

    const int tid = threadIdx.x;
    const int w = tid >> 5, ln = tid & 31;
    const int wm = (w >> 2) * 64;
    const int wn = (w & 3) * 32;
    const int rg = tid >> 3;
    const int ck = tid & 7;

    const float* Ab = A + (size_t)(row0 + rg) * DMODEL + ck * 4;
    const float* Bb = Bm + (size_t)(col0 + rg) * DMODEL + ck * 4;

    float acc[4][4][4];
#pragma unroll
    for (int i = 0; i < 4; i++)
#pragma unroll
        for (int j = 0; j < 4; j++)
#pragma unroll
            for (int t = 0; t < 4; t++) acc[i][j][t] = 0.f;

    const uint32_t uA = cvta_s(sA);
    const uint32_t uB = cvta_s(sB);

    float4 ar[4], br[4];
#pragma unroll
    for (int i = 0; i < 4; i++) {
        ar[i] = *(const float4*)(Ab + (size_t)i * 32 * DMODEL);
        br[i] = *(const float4*)(Bb + (size_t)i * 32 * DMODEL);
    }

    for (int s = 0; s < 2; s++) {          // K = 64
        store_rows_1(uA, ar, 4, rg, ck);
        store_rows_1(uB, br, 4, rg, ck);
        __syncthreads();

        if (s == 0) {
#pragma unroll
            for (int i = 0; i < 4; i++) {
                ar[i] = *(const float4*)(Ab + 32 + (size_t)i * 32 * DMODEL);
                br[i] = *(const float4*)(Bb + 32 + (size_t)i * 32 * DMODEL);
            }
        }

#pragma unroll
        for (int ks = 0; ks < 2; ks++) {
            uint32_t ah[4][4], bh[2][4];
#pragma unroll
            for (int i = 0; i < 4; i++) {
                uint32_t off = (uint32_t)((wm + i * 16 + (ln & 15)) * PITCH) * 2
                             + (uint32_t)ks * 32 + (uint32_t)(ln >> 4) * 16;
                ldsm4(ah[i], uA + off);
            }
#pragma unroll
            for (int g = 0; g < 2; g++) {
                uint32_t row = (uint32_t)(wn + g * 16 + ((ln >> 4) << 3) + (ln & 7));
                uint32_t off = row * PITCH * 2 + (uint32_t)ks * 32
                             + (uint32_t)((ln >> 3) & 1) * 16;
                ldsm4(bh[g], uB + off);
            }
#pragma unroll
            for (int i = 0; i < 4; i++)
#pragma unroll
                for (int j = 0; j < 4; j++)
                    mma_f16(acc[i][j], ah[i], &bh[j >> 1][(j & 1) * 2]);
        }
        __syncthreads();
    }

    // epilogue: exp + fp16 P write + row partials
    float rp0[4], rp1[4];
#pragma unroll
    for (int i = 0; i < 4; i++) { rp0[i] = 0.f; rp1[i] = 0.f; }

#pragma unroll
    for (int i = 0; i < 4; i++) {
        int r = wm + i * 16 + (ln >> 2);
        int gr = row0 + r;
#pragma unroll
        for (int j = 0; j < 4; j++) {
            int c = col0 + wn + j * 8 + 2 * (ln & 3);
            const unsigned char* mp = masks + ((size_t)b * SEQ + gr) * SEQ + c;
            uchar2 ma = *(const uchar2*)mp;
            uchar2 mb = *(const uchar2*)(mp + 8 * SEQ);
            float e00 = ma.x ? 0.f : __expf(0.125f * acc[i][j][0]);
            float e01 = ma.y ? 0.f : __expf(0.125f * acc[i][j][1]);
            float e10 = mb.x ? 0.f : __expf(0.125f * acc[i][j][2]);
            float e11 = mb.y ? 0.f : __expf(0.125f * acc[i][j][3]);
            rp0[i] += e00 + e01;
            rp1[i] += e10 + e11;
            __half2 p0 = __floats2half2_rn(e00, e01);
            __half2 p1 = __floats2half2_rn(e10, e11);
            *(__half2*)&g_p16[((size_t)z * SEQ + gr) * SEQ + c] = p0;
            *(__half2*)&g_p16[((size_t)z * SEQ + gr + 8) * SEQ + c] = p1;
        }
    }
#pragma unroll
    for (int i = 0; i < 4; i++) {
        rp0[i] += __shfl_xor_sync(0xffffffffu, rp0[i], 1);
        rp0[i] += __shfl_xor_sync(0xffffffffu, rp0[i], 2);
        rp1[i] += __shfl_xor_sync(0xffffffffu, rp1[i], 1);
        rp1[i] += __shfl_xor_sync(0xffffffffu, rp1[i], 2);
    }
    __syncthreads();
    float* sred = reinterpret_cast<float*>(sA);
    if ((ln & 3) == 0) {
#pragma unroll
        for (int i = 0; i < 4; i++) {
            int r = wm + i * 16 + (ln >> 2);
            sred[(w & 3) * 128 + r] = rp0[i];
            sred[(w & 3) * 128 + r + 8] = rp1[i];
        }
    }
    __syncthreads();
    if (tid < 128) {
        float ssum = sred[tid] + sred[128 + tid] + sred[256 + tid] + sred[384 + tid];
        g_rspart[(((size_t)z * SEQ) + row0 + tid) * 8 + blockIdx.x] = ssum;
    }
}

// ---------------------------------------------------------------------------
// rowinv = 1 / sum(partials)
// ---------------------------------------------------------------------------
__global__ void rowinv_kernel()
{
    int r = blockIdx.x * 256 + threadIdx.x;
    const float4* p = (const float4*)&g_rspart[(size_t)r * 8];
    float4 a = p[0], b = p[1];
    g_rowinv[r] = 1.f / (a.x + a.y + a.z + a.w + b.x + b.y + b.z + b.w);
}

// ---------------------------------------------------------------------------
// AV: exact R14 pipeline (32-wide stages, double-buffered, one sync/stage,
// float4 att write-back) with single-fp16 V (V-lo removed: 16 mma/stage).
// ---------------------------------------------------------------------------
__global__ void __launch_bounds__(256, 2) av_mma_kernel(float* __restrict__ att)
{
    extern __shared__ __align__(16) char dynsm[];
    const uint32_t sb = cvta_s(dynsm);
    const uint32_t uPa = sb + AV_OFF_P;
    const uint32_t uVa = sb + AV_OFF_V;

    int z = blockIdx.z;
    int b = z >> 4, h = z & 15;
    const float* V = g_vp + (size_t)b * SEQ * DMODEL + h * HD;
    float* C = g_ctx + (size_t)b * SEQ * DMODEL + h * HD;
    const int row0 = blockIdx.y * 128;

    const int tid = threadIdx.x;
    const int w = tid >> 5, ln = tid & 31;
    const int wm = (w >> 1) * 32;          // 4 warps in m
    const int wn = (w & 1) * 32;           // 2 warps in n
    const int prow = tid >> 1;             // 0..127 : P loader row
    const int pseg = tid & 1;              // 0/1 : 16-half segment
    const int vr = tid >> 4, vc = tid & 15;

    const __half* Pb = g_p16 + ((size_t)z * SEQ + row0 + prow) * SEQ + pseg * 16;
    float* attb = att + ((size_t)z * SEQ + row0 + prow) * SEQ + pseg * 16;
    const float invp = g_rowinv[((size_t)z << 10) + row0 + prow];
    const float* Vb = V + (size_t)vr * DMODEL + vc * 4;

    float acc[2][4][4];
#pragma unroll
    for (int i = 0; i < 2; i++)
#pragma unroll
        for (int j = 0; j < 4; j++)
#pragma unroll
            for (int t = 0; t < 4; t++) acc[i][j][t] = 0.f;

    uint4 pr0, pr1;
    float4 vrg[2];
    pr0 = *(const uint4*)(Pb);
    pr1 = *(const uint4*)(Pb + 8);
#pragma unroll
    for (int i = 0; i < 2; i++) vrg[i] = *(const float4*)(Vb + (size_t)i * 16 * DMODEL);

    const int NSTAGES = SEQ / 32;
    for (int s = 0; s < NSTAGES; s++) {
        const uint32_t pOff = (uint32_t)(s & 1) * SZP;
        const uint32_t vOff = (uint32_t)(s & 1) * SZV;

        // stage P (fp16) into smem buffer
        {
            uint32_t base = uPa + pOff + (uint32_t)(prow * PITCH + pseg * 16) * 2;
            sts4(base,      pr0.x, pr0.y, pr0.z, pr0.w);
            sts4(base + 16, pr1.x, pr1.y, pr1.z, pr1.w);
        }
        // stage V (fp32 -> single fp16) into smem buffer
#pragma unroll
        for (int i = 0; i < 2; i++) {
            int r = vr + 16 * i;
            uint32_t off2 = (uint32_t)(r * PITCHV + vc * 4) * 2;
            sts2(uVa + vOff + off2,
                 pack_h2(vrg[i].x, vrg[i].y), pack_h2(vrg[i].z, vrg[i].w));
        }
        // normalized att write-back (float4 x4, 64B-aligned base)
        {
            float* adst = attb + (size_t)s * 32;
            const uint32_t pw[8] = {pr0.x, pr0.y, pr0.z, pr0.w,
                                    pr1.x, pr1.y, pr1.z, pr1.w};
#pragma unroll
            for (int q4 = 0; q4 < 4; q4++) {
                float2 fa = __half22float2(*reinterpret_cast<const __half2*>(&pw[q4 * 2]));
                float2 fb = __half22float2(*reinterpret_cast<const __half2*>(&pw[q4 * 2 + 1]));
                *(float4*)(adst + q4 * 4) =
                    make_float4(fa.x * invp, fa.y * invp, fb.x * invp, fb.y * invp);
            }
        }
        __syncthreads();

        // prefetch next stage into regs (hidden under mma below)
        if (s + 1 < NSTAGES) {
            pr0 = *(const uint4*)(Pb + (size_t)(s + 1) * 32);
            pr1 = *(const uint4*)(Pb + (size_t)(s + 1) * 32 + 8);
            const float* Vn = Vb + (size_t)(s + 1) * 32 * DMODEL;
#pragma unroll
            for (int i = 0; i < 2; i++) vrg[i] = *(const float4*)(Vn + (size_t)i * 16 * DMODEL);
        }

        // compute on current buffer (single V term)
#pragma unroll
        for (int ks = 0; ks < 2; ks++) {
            uint32_t ah[2][4], bh[2][4];
#pragma unroll
            for (int i = 0; i < 2; i++) {
                uint32_t off = (uint32_t)((wm + i * 16 + (ln & 15)) * PITCH) * 2
                             + (uint32_t)ks * 32 + (uint32_t)(ln >> 4) * 16;
                ldsm4(ah[i], uPa + pOff + off);
            }
#pragma unroll
            for (int g = 0; g < 2; g++) {
                uint32_t rk = (uint32_t)(ks * 16 + (((ln >> 3) & 1) << 3) + (ln & 7));
                uint32_t nc = (uint32_t)(wn + g * 16 + ((ln >> 4) << 3));
                uint32_t off = rk * PITCHV * 2 + nc * 2;
                ldsm4t(bh[g], uVa + vOff + off);
            }
#pragma unroll
            for (int i = 0; i < 2; i++)
#pragma unroll
                for (int j = 0; j < 4; j++)
                    mma_f16(acc[i][j], ah[i], &bh[j >> 1][(j & 1) * 2]);
        }
    }

#pragma unroll
    for (int i = 0; i < 2; i++) {
        int r = row0 + wm + i * 16 + (ln >> 2);
        float iv0 = g_rowinv[((size_t)z << 10) + r];
        float iv1 = g_rowinv[((size_t)z << 10) + r + 8];
#pragma unroll
        for (int j = 0; j < 4; j++) {
            int c = wn + j * 8 + 2 * (ln & 3);
            *(float2*)&C[(size_t)r * DMODEL + c] =
                make_float2(acc[i][j][0] * iv0, acc[i][j][1] * iv0);
            *(float2*)&C[(size_t)(r + 8) * DMODEL + c] =
                make_float2(acc[i][j][2] * iv1, acc[i][j][3] * iv1);
        }
    }
}

// ---------------------------------------------------------------------------
// output = LayerNorm(qp + ctx) * g + b
// ---------------------------------------------------------------------------
__global__ void ln_kernel(float* __restrict__ out,
                          const float* __restrict__ gam,
                          const float* __restrict__ bet)
{
    __shared__ float reds[8];
    __shared__ float redq[8];
    __shared__ float stat[2];

    int row = blockIdx.x;
    const float* xq = g_qp + (size_t)row * DMODEL;
    const float* xc = g_ctx + (size_t)row * DMODEL;
    int j = threadIdx.x * 4;

    float4 a = *(const float4*)(xq + j);
    float4 c = *(const float4*)(xc + j);
    float x0 = a.x + c.x, x1 = a.y + c.y, x2 = a.z + c.z, x3 = a.w + c.w;

    float s = x0 + x1 + x2 + x3;
    float sq = x0 * x0 + x1 * x1 + x2 * x2 + x3 * x3;
#pragma unroll
    for (int o = 16; o; o >>= 1) {
        s += __shfl_xor_sync(0xffffffffu, s, o);
        sq += __shfl_xor_sync(0xffffffffu, sq, o);
    }
    if ((threadIdx.x & 31) == 0) { reds[threadIdx.x >> 5] = s; redq[threadIdx.x >> 5] = sq; }
    __syncthreads();
    if (threadIdx.x == 0) {
        float S = 0.f, Q = 0.f;
#pragma unroll
        for (int w = 0; w < 8; w++) { S += reds[w]; Q += redq[w]; }
        float mu = S * (1.0f / DMODEL);
        float var = Q * (1.0f / DMODEL) - mu * mu;
        stat[0] = mu;
        stat[1] = rsqrtf(var + 1e-6f);
    }
    __syncthreads();
    float mu = stat[0], r = stat[1];

    float4 g4 = *(const float4*)(gam + j);
    float4 b4 = *(const float4*)(bet + j);
    float4 o4;
    o4.x = (x0 - mu) * r * g4.x + b4.x;
    o4.y = (x1 - mu) * r * g4.y + b4.y;
    o4.z = (x2 - mu) * r * g4.z + b4.z;
    o4.w = (x3 - mu) * r * g4.w + b4.w;
    *(float4*)(out + (size_t)row * DMODEL + j) = o4;
}

// ---------------------------------------------------------------------------
extern "C" void kernel_launch(void* const* d_in, const int* in_sizes, int n_in,
                              void* d_out, int out_size)
{
    const float* q  = (const float*)d_in[0];
    const float* k  = (const float*)d_in[1];
    const float* v  = (const float*)d_in[2];
    const unsigned char* masks = (const unsigned char*)d_in[3];
    const float* Wq = (const float*)d_in[4];
    const float* bq = (const float*)d_in[5];
    const float* Wk = (const float*)d_in[6];
    const float* bk = (const float*)d_in[7];
    const float* Wv = (const float*)d_in[8];
    const float* bv = (const float*)d_in[9];
    const float* lng = (const float*)d_in[10];
    const float* lnb = (const float*)d_in[11];

    float* out = (float*)d_out;
    float* att = out + (size_t)BATCH * SEQ * DMODEL;

    cudaFuncSetAttribute(proj_mma_kernel,
                         cudaFuncAttributeMaxDynamicSharedMemorySize, PROJ_SMEM);
    cudaFuncSetAttribute(av_mma_kernel,
                         cudaFuncAttributeMaxDynamicSharedMemorySize, AV_SMEM);

    proj_mma_kernel<<<dim3(DMODEL / 64, NROWS / 128, 3), 256, PROJ_SMEM>>>(
        q, k, v, Wq, bq, Wk, bk, Wv, bv);
    scores_exp_kernel<<<dim3(SEQ / 128, SEQ / 128, BATCH * NH), 256>>>(masks);
    rowinv_kernel<<<256, 256>>>();
    av_mma_kernel<<<dim3(1, SEQ / 128, BATCH * NH), 256, AV_SMEM>>>(att);
    ln_kernel<<<NROWS, 256>>>(out, lng, lnb);
}